// round 1
// baseline (speedup 1.0000x reference)
#include <cuda_runtime.h>
#include <math.h>

#define NB   16
#define NI   127
#define NN   16129      // 127*127
#define NF   256
#define IMG  65536      // 256*256

// ---------------- scratch (static device globals; no runtime allocation) ----
static __device__ float  g_x[NB * NN];
static __device__ float  g_r[NB * NN];
static __device__ float2 g_FA[NB * IMG];
static __device__ float2 g_FB[NB * IMG];
static __device__ float2 g_C1[NB * 4 * IMG];
static __device__ float2 g_C2[NB * 4 * IMG];
static __device__ float2 g_part[256];

// ---------------- helpers ----------------------------------------------------
__device__ __forceinline__ int get_K(const int* ep) {
    int ei = *ep;
    int e;
    if (ei > 0 && ei <= 1000000) {
        e = ei;                                  // stored as int32
    } else {
        float ff = __int_as_float(ei);           // stored as float32
        e = (ff >= 1.0f && ff <= 1000000.0f) ? (int)ff : 120;
    }
    int K = (e - 1) / 40 + 1;
    if (K > 10) K = 10;
    if (K < 1)  K = 1;
    return K;
}

// 256-point Stockham radix-2 FFT in shared memory. 128 threads, results end in sA.
// sign = -1: forward DFT (e^{-2pi i jk/n});  sign = +1: inverse (unnormalized).
__device__ __forceinline__ void fft256(float2* sA, float2* sB, int t, float sign) {
    float2* src = sA;
    float2* dst = sB;
    int n = 256, s = 1;
#pragma unroll
    for (int st = 0; st < 8; ++st) {
        int m = n >> 1;
        int p = t / s;
        int q = t - p * s;
        float2 a  = src[q + s * p];
        float2 bb = src[q + s * (p + m)];
        float ang = sign * (6.283185307179586f * (float)p / (float)n);
        float sw, cw;
        sincosf(ang, &sw, &cw);
        float dx = a.x - bb.x, dy = a.y - bb.y;
        dst[q + s * (2 * p)]     = make_float2(a.x + bb.x, a.y + bb.y);
        dst[q + s * (2 * p + 1)] = make_float2(dx * cw - dy * sw, dx * sw + dy * cw);
        __syncthreads();
        float2* tmp = src; src = dst; dst = tmp;
        n >>= 1; s <<= 1;
    }
}

// ---------------- kernels ----------------------------------------------------
__global__ void zero_x_kernel() {
    int i = blockIdx.x * blockDim.x + threadIdx.x;
    if (i < NB * NN) g_x[i] = 0.0f;
}

// One CTA per batch sample: 20 Jacobi sweeps fully in shared memory, then
// writes x and r = f - A x. 512 threads: tx = column (0..126), ty = row strip.
__global__ void jacobi_kernel(const float* __restrict__ f, const float* __restrict__ kA,
                              const int* __restrict__ ep, int iter) {
    if (iter >= get_K(ep)) return;
    extern __shared__ float smem[];
    float* xs0 = smem;
    float* xs1 = smem + NN;
    int b  = blockIdx.x;
    int t  = threadIdx.x;
    int tx = t & 127;
    int ty = t >> 7;                      // 0..3
    const float* ka = kA + b * 9;
    float k0 = ka[0], k1 = ka[1], k2 = ka[2], k3 = ka[3], k4 = ka[4];
    float k5 = ka[5], k6 = ka[6], k7 = ka[7], k8 = ka[8];
    float tau = 0.5f / k4;

    for (int i = t; i < NN; i += 512) xs0[i] = g_x[b * NN + i];
    __syncthreads();

    int y0 = ty * 32;
    int y1 = min(127, y0 + 32);

    float freg[32];
    if (tx < 127) {
        for (int i = 0; i < 32; ++i) {
            int y = y0 + i;
            if (y < y1) freg[i] = f[b * NN + y * 127 + tx];
        }
    }

    float* cur = xs0;
    float* nxt = xs1;
    for (int it = 0; it < 20; ++it) {
        if (tx < 127) {
            float am, a0, ap, bm, b0, bp;
            if (y0 > 0) {
                int r_ = (y0 - 1) * 127;
                am = (tx > 0)   ? cur[r_ + tx - 1] : 0.0f;
                a0 = cur[r_ + tx];
                ap = (tx < 126) ? cur[r_ + tx + 1] : 0.0f;
            } else { am = a0 = ap = 0.0f; }
            {
                int r_ = y0 * 127;
                bm = (tx > 0)   ? cur[r_ + tx - 1] : 0.0f;
                b0 = cur[r_ + tx];
                bp = (tx < 126) ? cur[r_ + tx + 1] : 0.0f;
            }
            for (int i = 0; i < 32; ++i) {
                int y = y0 + i;
                if (y >= y1) break;
                float cm, c0, cp;
                if (y + 1 < 127) {
                    int r_ = (y + 1) * 127;
                    cm = (tx > 0)   ? cur[r_ + tx - 1] : 0.0f;
                    c0 = cur[r_ + tx];
                    cp = (tx < 126) ? cur[r_ + tx + 1] : 0.0f;
                } else { cm = c0 = cp = 0.0f; }
                float ax = k0 * am + k1 * a0 + k2 * ap
                         + k3 * bm + k4 * b0 + k5 * bp
                         + k6 * cm + k7 * c0 + k8 * cp;
                nxt[y * 127 + tx] = b0 + tau * (freg[i] - ax);
                am = bm; a0 = b0; ap = bp;
                bm = cm; b0 = c0; bp = cp;
            }
        }
        __syncthreads();
        float* tswap = cur; cur = nxt; nxt = tswap;
    }

    // r = f - A x, write back x and r
    if (tx < 127) {
        float am, a0, ap, bm, b0, bp;
        if (y0 > 0) {
            int r_ = (y0 - 1) * 127;
            am = (tx > 0)   ? cur[r_ + tx - 1] : 0.0f;
            a0 = cur[r_ + tx];
            ap = (tx < 126) ? cur[r_ + tx + 1] : 0.0f;
        } else { am = a0 = ap = 0.0f; }
        {
            int r_ = y0 * 127;
            bm = (tx > 0)   ? cur[r_ + tx - 1] : 0.0f;
            b0 = cur[r_ + tx];
            bp = (tx < 126) ? cur[r_ + tx + 1] : 0.0f;
        }
        for (int i = 0; i < 32; ++i) {
            int y = y0 + i;
            if (y >= y1) break;
            float cm, c0, cp;
            if (y + 1 < 127) {
                int r_ = (y + 1) * 127;
                cm = (tx > 0)   ? cur[r_ + tx - 1] : 0.0f;
                c0 = cur[r_ + tx];
                cp = (tx < 126) ? cur[r_ + tx + 1] : 0.0f;
            } else { cm = c0 = cp = 0.0f; }
            float ax = k0 * am + k1 * a0 + k2 * ap
                     + k3 * bm + k4 * b0 + k5 * bp
                     + k6 * cm + k7 * c0 + k8 * cp;
            int p = y * 127 + tx;
            g_x[b * NN + p] = b0;
            g_r[b * NN + p] = freg[i] - ax;
            am = bm; a0 = b0; ap = bp;
            bm = cm; b0 = c0; bp = cp;
        }
    }
}

// ifft2 pass 1: build odd-symmetric expansion of r on the fly, inverse FFT along x.
__global__ void fft_row_expand(const int* __restrict__ ep, int iter) {
    if (iter >= get_K(ep)) return;
    __shared__ float2 s0[256], s1[256];
    int b = blockIdx.y, y = blockIdx.x, t = threadIdx.x;
    float2* orow = g_FA + (b * 256 + y) * 256;
    if (y == 0 || y == 128) {
        orow[t]       = make_float2(0.0f, 0.0f);
        orow[t + 128] = make_float2(0.0f, 0.0f);
        return;
    }
    float sy; int ry;
    if (y < 128) { sy = 1.0f;  ry = y - 1;  }
    else         { sy = -1.0f; ry = 255 - y; }
    const float* rrow = g_r + (b * NN + ry * 127);
    for (int x = t; x < 256; x += 128) {
        float v = 0.0f;
        if (x >= 1 && x <= 127)      v =  sy * rrow[x - 1];
        else if (x >= 129)           v = -sy * rrow[255 - x];
        s0[x] = make_float2(v, 0.0f);
    }
    __syncthreads();
    fft256(s0, s1, t, 1.0f);
    orow[t]       = s0[t];
    orow[t + 128] = s0[t + 128];
}

// ifft2 pass 2: inverse FFT along y, scale 1/65536, write with fftshift (idx^128).
__global__ void fft_col_inv(const int* __restrict__ ep, int iter) {
    if (iter >= get_K(ep)) return;
    __shared__ float2 s0[256], s1[256];
    int b = blockIdx.y, x = blockIdx.x, t = threadIdx.x;
    s0[t]       = g_FA[(b * 256 + t) * 256 + x];
    s0[t + 128] = g_FA[(b * 256 + t + 128) * 256 + x];
    __syncthreads();
    fft256(s0, s1, t, 1.0f);
    const float sc = 1.0f / 65536.0f;
    int xo = x ^ 128;
    g_FB[(b * 256 + (t ^ 128)) * 256 + xo] = make_float2(s0[t].x * sc,       s0[t].y * sc);
    g_FB[(b * 256 + t)         * 256 + xo] = make_float2(s0[t + 128].x * sc, s0[t + 128].y * sc);
}

// Complex grouped 3x3 conv (cross-correlation, SAME zero pad), optional adjoint
// weight transform (swap io channels, transpose 3x3, conj) and theta multiply.
template <int CIN, int COUT, bool ADJ, bool THETA>
__global__ void conv_kernel(const float2* __restrict__ in, float2* __restrict__ out,
                            const float* __restrict__ wr, const float* __restrict__ wi,
                            const float* __restrict__ thr, const float* __restrict__ thi,
                            const int* __restrict__ ep, int iter) {
    if (iter >= get_K(ep)) return;
    __shared__ float2 Wsm[CIN * 9 * COUT];
    int b   = blockIdx.z;
    int tid = threadIdx.y * 32 + threadIdx.x;
    if (tid < CIN * 9 * COUT) {
        int ci = tid / (9 * COUT);
        int kk = (tid / COUT) % 9;
        int co = tid % COUT;
        int ky = kk / 3, kx = kk % 3;
        float wre, wim;
        if (!ADJ) {
            int j = ((b * COUT + co) * CIN + ci) * 9 + ky * 3 + kx;
            wre = wr[j]; wim = wi[j];
        } else {
            int j = ((b * CIN + ci) * COUT + co) * 9 + kx * 3 + ky;
            wre = wr[j]; wim = -wi[j];
        }
        Wsm[tid] = make_float2(wre, wim);
    }
    __syncthreads();

    int x = blockIdx.x * 32 + threadIdx.x;
    int y = blockIdx.y * 8  + threadIdx.y;

    float2 acc[COUT];
#pragma unroll
    for (int c = 0; c < COUT; ++c) acc[c] = make_float2(0.0f, 0.0f);

    const float2* inb = in + (size_t)b * CIN * IMG;
#pragma unroll
    for (int ci = 0; ci < CIN; ++ci) {
        const float2* ip = inb + ci * IMG;
#pragma unroll
        for (int ky = 0; ky < 3; ++ky) {
            int yy = y + ky - 1;
            if ((unsigned)yy < 256u) {
#pragma unroll
                for (int kx = 0; kx < 3; ++kx) {
                    int xx = x + kx - 1;
                    if ((unsigned)xx < 256u) {
                        float2 v = ip[yy * 256 + xx];
                        const float2* wp = &Wsm[(ci * 9 + ky * 3 + kx) * COUT];
#pragma unroll
                        for (int co = 0; co < COUT; ++co) {
                            float2 w = wp[co];
                            acc[co].x += v.x * w.x - v.y * w.y;
                            acc[co].y += v.x * w.y + v.y * w.x;
                        }
                    }
                }
            }
        }
    }

    float2 th = make_float2(0.0f, 0.0f);
    if (THETA) th = make_float2(thr[b * IMG + y * 256 + x], thi[b * IMG + y * 256 + x]);

    float2* ob = out + (size_t)b * COUT * IMG + y * 256 + x;
#pragma unroll
    for (int co = 0; co < COUT; ++co) {
        float2 v = acc[co];
        if (THETA) v = make_float2(v.x * th.x - v.y * th.y, v.x * th.y + v.y * th.x);
        ob[co * IMG] = v;
    }
}

// fft2 pass 1: ifftshift on read (idx^128), forward FFT along x.
__global__ void fft_row_fwd(const int* __restrict__ ep, int iter) {
    if (iter >= get_K(ep)) return;
    __shared__ float2 s0[256], s1[256];
    int b = blockIdx.y, y = blockIdx.x, t = threadIdx.x;
    const float2* irow = g_FB + (b * 256 + (y ^ 128)) * 256;
    s0[t]       = irow[t + 128];   // (t)^128
    s0[t + 128] = irow[t];         // (t+128)^128
    __syncthreads();
    fft256(s0, s1, t, -1.0f);
    float2* orow = g_FA + (b * 256 + y) * 256;
    orow[t]       = s0[t];
    orow[t + 128] = s0[t + 128];
}

// fft2 pass 2: forward FFT along y, take real part, crop to 127x127, accumulate into x.
__global__ void fft_col_fwd_accum(const int* __restrict__ ep, int iter) {
    if (iter >= get_K(ep)) return;
    __shared__ float2 s0[256], s1[256];
    int b = blockIdx.y, x = blockIdx.x, t = threadIdx.x;   // x in [0,127)
    s0[t]       = g_FA[(b * 256 + t) * 256 + x];
    s0[t + 128] = g_FA[(b * 256 + t + 128) * 256 + x];
    __syncthreads();
    fft256(s0, s1, t, -1.0f);
    if (t < 127) g_x[b * NN + t * 127 + x] += s0[t].x;
}

// Final residual norm: per-block partial sums of r^2 and f^2.
__global__ void norm_partial(const float* __restrict__ f, const float* __restrict__ kA) {
    __shared__ float sr_s[256], sf_s[256];
    float sr = 0.0f, sf = 0.0f;
    for (int idx = blockIdx.x * 256 + threadIdx.x; idx < NB * NN; idx += 256 * 256) {
        int b = idx / NN;
        int p = idx - b * NN;
        int y = p / 127, x = p - y * 127;
        const float* ka = kA + b * 9;
        const float* xb = g_x + b * NN;
        float s = 0.0f;
        if (y > 0) {
            if (x > 0)   s += ka[0] * xb[p - 128];
            s += ka[1] * xb[p - 127];
            if (x < 126) s += ka[2] * xb[p - 126];
        }
        if (x > 0)   s += ka[3] * xb[p - 1];
        s += ka[4] * xb[p];
        if (x < 126) s += ka[5] * xb[p + 1];
        if (y < 126) {
            if (x > 0)   s += ka[6] * xb[p + 126];
            s += ka[7] * xb[p + 127];
            if (x < 126) s += ka[8] * xb[p + 128];
        }
        float fv = f[idx];
        float rv = fv - s;
        sr += rv * rv;
        sf += fv * fv;
    }
    sr_s[threadIdx.x] = sr;
    sf_s[threadIdx.x] = sf;
    __syncthreads();
    for (int o = 128; o > 0; o >>= 1) {
        if (threadIdx.x < o) {
            sr_s[threadIdx.x] += sr_s[threadIdx.x + o];
            sf_s[threadIdx.x] += sf_s[threadIdx.x + o];
        }
        __syncthreads();
    }
    if (threadIdx.x == 0) g_part[blockIdx.x] = make_float2(sr_s[0], sf_s[0]);
}

__global__ void norm_final(float* __restrict__ out) {
    __shared__ float sr_s[256], sf_s[256];
    float2 v = g_part[threadIdx.x];
    sr_s[threadIdx.x] = v.x;
    sf_s[threadIdx.x] = v.y;
    __syncthreads();
    for (int o = 128; o > 0; o >>= 1) {
        if (threadIdx.x < o) {
            sr_s[threadIdx.x] += sr_s[threadIdx.x + o];
            sf_s[threadIdx.x] += sf_s[threadIdx.x + o];
        }
        __syncthreads();
    }
    if (threadIdx.x == 0) out[0] = sqrtf(sr_s[0] / sf_s[0]);
}

// ---------------- launch ------------------------------------------------------
extern "C" void kernel_launch(void* const* d_in, const int* in_sizes, int n_in,
                              void* d_out, int out_size) {
    (void)in_sizes; (void)n_in; (void)out_size;
    const float* f   = (const float*)d_in[0];
    const float* kA  = (const float*)d_in[1];
    const float* w1r = (const float*)d_in[2];
    const float* w1i = (const float*)d_in[3];
    const float* w2r = (const float*)d_in[4];
    const float* w2i = (const float*)d_in[5];
    const float* w3r = (const float*)d_in[6];
    const float* w3i = (const float*)d_in[7];
    const float* thr = (const float*)d_in[8];
    const float* thi = (const float*)d_in[9];
    const int*   ep  = (const int*)d_in[10];
    float* out = (float*)d_out;

    void *pFA = nullptr, *pFB = nullptr, *pC1 = nullptr, *pC2 = nullptr;
    cudaGetSymbolAddress(&pFA, g_FA);
    cudaGetSymbolAddress(&pFB, g_FB);
    cudaGetSymbolAddress(&pC1, g_C1);
    cudaGetSymbolAddress(&pC2, g_C2);

    cudaFuncSetAttribute(jacobi_kernel,
                         cudaFuncAttributeMaxDynamicSharedMemorySize, 2 * NN * 4);

    zero_x_kernel<<<(NB * NN + 255) / 256, 256>>>();

    dim3 cb(32, 8), cg(8, 32, NB);
    for (int it = 0; it < 3; ++it) {
        jacobi_kernel<<<NB, 512, 2 * NN * 4>>>(f, kA, ep, it);
        fft_row_expand<<<dim3(256, NB), 128>>>(ep, it);
        fft_col_inv<<<dim3(256, NB), 128>>>(ep, it);
        conv_kernel<1, 4, false, false><<<cg, cb>>>((const float2*)pFB, (float2*)pC1,
                                                    w1r, w1i, nullptr, nullptr, ep, it);
        conv_kernel<4, 4, false, false><<<cg, cb>>>((const float2*)pC1, (float2*)pC2,
                                                    w2r, w2i, nullptr, nullptr, ep, it);
        conv_kernel<4, 1, false, true ><<<cg, cb>>>((const float2*)pC2, (float2*)pFA,
                                                    w3r, w3i, thr, thi, ep, it);
        conv_kernel<1, 4, true,  false><<<cg, cb>>>((const float2*)pFA, (float2*)pC1,
                                                    w3r, w3i, nullptr, nullptr, ep, it);
        conv_kernel<4, 4, true,  false><<<cg, cb>>>((const float2*)pC1, (float2*)pC2,
                                                    w2r, w2i, nullptr, nullptr, ep, it);
        conv_kernel<4, 1, true,  false><<<cg, cb>>>((const float2*)pC2, (float2*)pFB,
                                                    w1r, w1i, nullptr, nullptr, ep, it);
        fft_row_fwd<<<dim3(256, NB), 128>>>(ep, it);
        fft_col_fwd_accum<<<dim3(127, NB), 128>>>(ep, it);
    }

    norm_partial<<<256, 256>>>(f, kA);
    norm_final<<<1, 256>>>(out);
}

// round 2
// speedup vs baseline: 1.1141x; 1.1141x over previous
#include <cuda_runtime.h>
#include <math.h>

#define NB   16
#define NI   127
#define NN   16129      // 127*127
#define IMG  65536      // 256*256

// ---------------- scratch (static device globals) ----------------------------
static __device__ float  g_x[NB * NN];
static __device__ float  g_r[NB * NN];
static __device__ float2 g_FA[NB * IMG];
static __device__ float2 g_FB[NB * IMG];
static __device__ float2 g_part[256];

// ---------------- helpers ----------------------------------------------------
__device__ __forceinline__ int get_K(const int* ep) {
    int ei = *ep;
    int e;
    if (ei > 0 && ei <= 1000000) {
        e = ei;
    } else {
        float ff = __int_as_float(ei);
        e = (ff >= 1.0f && ff <= 1000000.0f) ? (int)ff : 120;
    }
    int K = (e - 1) / 40 + 1;
    if (K > 10) K = 10;
    if (K < 1)  K = 1;
    return K;
}

__device__ __forceinline__ int rev8(int x) { return (int)(__brev((unsigned)x) >> 24); }

// Build 128-entry twiddle table: tw[k] = exp(sign * 2*pi*i * k / 256)
__device__ __forceinline__ void build_tw(float2* tw, int tid, float sign) {
    if (tid < 128) {
        float s, c;
        __sincosf(sign * 6.283185307179586f * (float)tid * (1.0f / 256.0f), &s, &c);
        tw[tid] = make_float2(c, s);
    }
}

// In-place 256-pt DIT FFT over bit-reversed-loaded data; 128 threads, 1 bfly each.
__device__ __forceinline__ void fft256_ip(float2* s, const float2* tw, int t) {
#pragma unroll
    for (int st = 1; st <= 8; ++st) {
        int mh  = 1 << (st - 1);
        int idx = ((t >> (st - 1)) << st) | (t & (mh - 1));
        int twi = (t & (mh - 1)) << (8 - st);
        float2 w = tw[twi];
        float2 u = s[idx];
        float2 v = s[idx + mh];
        float vr = v.x * w.x - v.y * w.y;
        float vi = v.x * w.y + v.y * w.x;
        s[idx]      = make_float2(u.x + vr, u.y + vi);
        s[idx + mh] = make_float2(u.x - vr, u.y - vi);
        __syncthreads();
    }
}

// ---------------- kernels ----------------------------------------------------
__global__ void zero_x_kernel() {
    int i = blockIdx.x * blockDim.x + threadIdx.x;
    if (i < NB * NN) g_x[i] = 0.0f;
}

// One CTA per sample: 20 Jacobi sweeps in shared memory, writes x and r=f-Ax.
__global__ void jacobi_kernel(const float* __restrict__ f, const float* __restrict__ kA,
                              const int* __restrict__ ep, int iter) {
    if (iter >= get_K(ep)) return;
    extern __shared__ float smem[];
    float* xs0 = smem;
    float* xs1 = smem + NN;
    int b  = blockIdx.x;
    int t  = threadIdx.x;
    int tx = t & 127;
    int ty = t >> 7;
    const float* ka = kA + b * 9;
    float k0 = ka[0], k1 = ka[1], k2 = ka[2], k3 = ka[3], k4 = ka[4];
    float k5 = ka[5], k6 = ka[6], k7 = ka[7], k8 = ka[8];
    float tau = 0.5f / k4;

    for (int i = t; i < NN; i += 512) xs0[i] = g_x[b * NN + i];
    __syncthreads();

    int y0 = ty * 32;
    int y1 = min(127, y0 + 32);

    float freg[32];
    if (tx < 127) {
        for (int i = 0; i < 32; ++i) {
            int y = y0 + i;
            if (y < y1) freg[i] = f[b * NN + y * 127 + tx];
        }
    }

    float* cur = xs0;
    float* nxt = xs1;
    for (int it = 0; it < 20; ++it) {
        if (tx < 127) {
            float am, a0, ap, bm, b0, bp;
            if (y0 > 0) {
                int r_ = (y0 - 1) * 127;
                am = (tx > 0)   ? cur[r_ + tx - 1] : 0.0f;
                a0 = cur[r_ + tx];
                ap = (tx < 126) ? cur[r_ + tx + 1] : 0.0f;
            } else { am = a0 = ap = 0.0f; }
            {
                int r_ = y0 * 127;
                bm = (tx > 0)   ? cur[r_ + tx - 1] : 0.0f;
                b0 = cur[r_ + tx];
                bp = (tx < 126) ? cur[r_ + tx + 1] : 0.0f;
            }
            for (int i = 0; i < 32; ++i) {
                int y = y0 + i;
                if (y >= y1) break;
                float cm, c0, cp;
                if (y + 1 < 127) {
                    int r_ = (y + 1) * 127;
                    cm = (tx > 0)   ? cur[r_ + tx - 1] : 0.0f;
                    c0 = cur[r_ + tx];
                    cp = (tx < 126) ? cur[r_ + tx + 1] : 0.0f;
                } else { cm = c0 = cp = 0.0f; }
                float ax = k0 * am + k1 * a0 + k2 * ap
                         + k3 * bm + k4 * b0 + k5 * bp
                         + k6 * cm + k7 * c0 + k8 * cp;
                nxt[y * 127 + tx] = b0 + tau * (freg[i] - ax);
                am = bm; a0 = b0; ap = bp;
                bm = cm; b0 = c0; bp = cp;
            }
        }
        __syncthreads();
        float* tswap = cur; cur = nxt; nxt = tswap;
    }

    if (tx < 127) {
        float am, a0, ap, bm, b0, bp;
        if (y0 > 0) {
            int r_ = (y0 - 1) * 127;
            am = (tx > 0)   ? cur[r_ + tx - 1] : 0.0f;
            a0 = cur[r_ + tx];
            ap = (tx < 126) ? cur[r_ + tx + 1] : 0.0f;
        } else { am = a0 = ap = 0.0f; }
        {
            int r_ = y0 * 127;
            bm = (tx > 0)   ? cur[r_ + tx - 1] : 0.0f;
            b0 = cur[r_ + tx];
            bp = (tx < 126) ? cur[r_ + tx + 1] : 0.0f;
        }
        for (int i = 0; i < 32; ++i) {
            int y = y0 + i;
            if (y >= y1) break;
            float cm, c0, cp;
            if (y + 1 < 127) {
                int r_ = (y + 1) * 127;
                cm = (tx > 0)   ? cur[r_ + tx - 1] : 0.0f;
                c0 = cur[r_ + tx];
                cp = (tx < 126) ? cur[r_ + tx + 1] : 0.0f;
            } else { cm = c0 = cp = 0.0f; }
            float ax = k0 * am + k1 * a0 + k2 * ap
                     + k3 * bm + k4 * b0 + k5 * bp
                     + k6 * cm + k7 * c0 + k8 * cp;
            int p = y * 127 + tx;
            g_x[b * NN + p] = b0;
            g_r[b * NN + p] = freg[i] - ax;
            am = bm; a0 = b0; ap = bp;
            bm = cm; b0 = c0; bp = cp;
        }
    }
}

// ifft2 pass 1: build odd-symmetric expansion of r, inverse FFT along x.
__global__ void fft_row_expand(const int* __restrict__ ep, int iter) {
    if (iter >= get_K(ep)) return;
    __shared__ float2 s[256];
    __shared__ float2 tw[128];
    int b = blockIdx.y, y = blockIdx.x, t = threadIdx.x;
    float2* orow = g_FA + (b * 256 + y) * 256;
    if (y == 0 || y == 128) {
        orow[t]       = make_float2(0.0f, 0.0f);
        orow[t + 128] = make_float2(0.0f, 0.0f);
        return;
    }
    build_tw(tw, t, 1.0f);
    float sy; int ry;
    if (y < 128) { sy = 1.0f;  ry = y - 1;  }
    else         { sy = -1.0f; ry = 255 - y; }
    const float* rrow = g_r + (b * NN + ry * 127);
#pragma unroll
    for (int k = 0; k < 2; ++k) {
        int p = t + k * 128;
        float v = 0.0f;
        if (p >= 1 && p <= 127)  v =  sy * rrow[p - 1];
        else if (p >= 129)       v = -sy * rrow[255 - p];
        s[rev8(p)] = make_float2(v, 0.0f);
    }
    __syncthreads();
    fft256_ip(s, tw, t);
    orow[t]       = s[t];
    orow[t + 128] = s[t + 128];
}

// ifft2 pass 2: tiled column FFT (32 cols/block), scale, write with fftshift.
__global__ void fft_col_inv(const int* __restrict__ ep, int iter) {
    if (iter >= get_K(ep)) return;
    extern __shared__ float2 csm[];       // [256*32] data + [128] tw
    float2* s  = csm;
    float2* tw = csm + 256 * 32;
    int b  = blockIdx.y;
    int tx = threadIdx.x, ty = threadIdx.y;
    int tid = ty * 32 + tx;
    int x = blockIdx.x * 32 + tx;
    build_tw(tw, tid, 1.0f);
    for (int r = ty; r < 256; r += 8)
        s[rev8(r) * 32 + tx] = g_FA[(b * 256 + r) * 256 + x];
    __syncthreads();
#pragma unroll
    for (int st = 1; st <= 8; ++st) {
        int mh = 1 << (st - 1);
#pragma unroll
        for (int k = 0; k < 16; ++k) {
            int i   = ty * 16 + k;
            int idx = ((i >> (st - 1)) << st) | (i & (mh - 1));
            int twi = (i & (mh - 1)) << (8 - st);
            float2 w = tw[twi];
            float2 u = s[idx * 32 + tx];
            float2 v = s[(idx + mh) * 32 + tx];
            float vr = v.x * w.x - v.y * w.y;
            float vi = v.x * w.y + v.y * w.x;
            s[idx * 32 + tx]        = make_float2(u.x + vr, u.y + vi);
            s[(idx + mh) * 32 + tx] = make_float2(u.x - vr, u.y - vi);
        }
        __syncthreads();
    }
    const float sc = 1.0f / 65536.0f;
    int xo = x ^ 128;
    for (int r = ty; r < 256; r += 8) {
        float2 v = s[r * 32 + tx];
        g_FB[(b * 256 + (r ^ 128)) * 256 + xo] = make_float2(v.x * sc, v.y * sc);
    }
}

// Fused 3-conv stack: in(1ch) -> 4ch -> 4ch -> 1ch, tiles of 32x32, halo 3.
// ADJ=false: weights (w1,w2,w3), output *= theta, write g_FA.
// ADJ=true : weights (tconj(w3),tconj(w2),tconj(w1)), write g_FB.
template <bool ADJ>
__global__ void __launch_bounds__(256, 2)
fused_stack(const float2* __restrict__ in, float2* __restrict__ out,
            const float* __restrict__ w1r, const float* __restrict__ w1i,
            const float* __restrict__ w2r, const float* __restrict__ w2i,
            const float* __restrict__ w3r, const float* __restrict__ w3i,
            const float* __restrict__ thr, const float* __restrict__ thi,
            const int* __restrict__ ep, int iter) {
    if (iter >= get_K(ep)) return;
    extern __shared__ float2 sm[];
    float2* T1  = sm;                 // 4 * 36*36 = 5184
    float2* BUF = sm + 5184;          // max(38*38, 4*34*34) = 4624 (IN then T2)
    float2* Wa  = sm + 5184 + 4624;   // [9][4]
    float2* Wb  = Wa + 36;            // [4][9][4]
    float2* Wc  = Wa + 180;           // [4][9]

    int b   = blockIdx.z;
    int ox  = blockIdx.x * 32;
    int oy  = blockIdx.y * 32;
    int tid = threadIdx.x;

    // ---- load weights ----
    if (tid < 216) {
        if (tid < 36) {
            int tap = tid >> 2, co = tid & 3;
            if (!ADJ) {
                int j = (b * 4 + co) * 9 + tap;
                Wa[tid] = make_float2(w1r[j], w1i[j]);
            } else {
                int tt = (tap % 3) * 3 + tap / 3;
                int j = (b * 4 + co) * 9 + tt;
                Wa[tid] = make_float2(w3r[j], -w3i[j]);
            }
        } else if (tid < 180) {
            int u = tid - 36;
            int ci = u / 36, tap = (u % 36) >> 2, co = u & 3;
            if (!ADJ) {
                int j = ((b * 4 + co) * 4 + ci) * 9 + tap;
                Wb[u] = make_float2(w2r[j], w2i[j]);
            } else {
                int tt = (tap % 3) * 3 + tap / 3;
                int j = ((b * 4 + ci) * 4 + co) * 9 + tt;
                Wb[u] = make_float2(w2r[j], -w2i[j]);
            }
        } else {
            int u = tid - 180;
            int ci = u / 9, tap = u % 9;
            if (!ADJ) {
                int j = (b * 4 + ci) * 9 + tap;
                Wc[u] = make_float2(w3r[j], w3i[j]);
            } else {
                int tt = (tap % 3) * 3 + tap / 3;
                int j = (b * 4 + ci) * 9 + tt;
                Wc[u] = make_float2(w1r[j], -w1i[j]);
            }
        }
    }

    // ---- load input tile 38x38 with zero pad ----
    const float2* inb = in + (size_t)b * IMG;
    for (int i = tid; i < 38 * 38; i += 256) {
        int iy = i / 38, ix = i % 38;
        int gy = oy - 3 + iy, gx = ox - 3 + ix;
        float2 v = make_float2(0.0f, 0.0f);
        if ((unsigned)gy < 256u && (unsigned)gx < 256u) v = inb[gy * 256 + gx];
        BUF[i] = v;
    }
    __syncthreads();

    // ---- stage 1: 1 -> 4, region 36x36 (img origin oy-2, ox-2) ----
    for (int p = tid; p < 1296; p += 256) {
        int py = p / 36, px = p % 36;
        int gy = oy - 2 + py, gx = ox - 2 + px;
        float2 a0 = make_float2(0.f, 0.f), a1 = a0, a2 = a0, a3 = a0;
        if ((unsigned)gy < 256u && (unsigned)gx < 256u) {
            int base = py * 38 + px;
#pragma unroll
            for (int tap = 0; tap < 9; ++tap) {
                float2 v = BUF[base + (tap / 3) * 38 + tap % 3];
                float2 w;
                w = Wa[tap * 4 + 0]; a0.x += v.x*w.x - v.y*w.y; a0.y += v.x*w.y + v.y*w.x;
                w = Wa[tap * 4 + 1]; a1.x += v.x*w.x - v.y*w.y; a1.y += v.x*w.y + v.y*w.x;
                w = Wa[tap * 4 + 2]; a2.x += v.x*w.x - v.y*w.y; a2.y += v.x*w.y + v.y*w.x;
                w = Wa[tap * 4 + 3]; a3.x += v.x*w.x - v.y*w.y; a3.y += v.x*w.y + v.y*w.x;
            }
        }
        T1[0 * 1296 + p] = a0;
        T1[1 * 1296 + p] = a1;
        T1[2 * 1296 + p] = a2;
        T1[3 * 1296 + p] = a3;
    }
    __syncthreads();

    // ---- stage 2: 4 -> 4, region 34x34 (img origin oy-1, ox-1), into BUF ----
    {
        float2 acc[5][4];
        int bidx[5];
        bool val[5];
#pragma unroll
        for (int k = 0; k < 5; ++k) {
            int p = tid + k * 256;
            val[k] = p < 1156;
            int py = p / 34, px = p % 34;
            bidx[k] = py * 36 + px;
#pragma unroll
            for (int c = 0; c < 4; ++c) acc[k][c] = make_float2(0.f, 0.f);
        }
#pragma unroll
        for (int ci = 0; ci < 4; ++ci) {
            const float2* Tci = T1 + ci * 1296;
#pragma unroll
            for (int tap = 0; tap < 9; ++tap) {
                float2 w0 = Wb[(ci * 9 + tap) * 4 + 0];
                float2 w1 = Wb[(ci * 9 + tap) * 4 + 1];
                float2 w2 = Wb[(ci * 9 + tap) * 4 + 2];
                float2 w3 = Wb[(ci * 9 + tap) * 4 + 3];
                int off = (tap / 3) * 36 + tap % 3;
#pragma unroll
                for (int k = 0; k < 5; ++k) {
                    if (val[k]) {
                        float2 v = Tci[bidx[k] + off];
                        acc[k][0].x += v.x*w0.x - v.y*w0.y; acc[k][0].y += v.x*w0.y + v.y*w0.x;
                        acc[k][1].x += v.x*w1.x - v.y*w1.y; acc[k][1].y += v.x*w1.y + v.y*w1.x;
                        acc[k][2].x += v.x*w2.x - v.y*w2.y; acc[k][2].y += v.x*w2.y + v.y*w2.x;
                        acc[k][3].x += v.x*w3.x - v.y*w3.y; acc[k][3].y += v.x*w3.y + v.y*w3.x;
                    }
                }
            }
        }
        __syncthreads();  // BUF (IN) fully consumed via T1 already; T1 reads done
#pragma unroll
        for (int k = 0; k < 5; ++k) {
            if (val[k]) {
                int p = tid + k * 256;
                int py = p / 34, px = p % 34;
                int gy = oy - 1 + py, gx = ox - 1 + px;
                bool inb2 = ((unsigned)gy < 256u) && ((unsigned)gx < 256u);
#pragma unroll
                for (int c = 0; c < 4; ++c)
                    BUF[c * 1156 + p] = inb2 ? acc[k][c] : make_float2(0.f, 0.f);
            }
        }
    }
    __syncthreads();

    // ---- stage 3: 4 -> 1, region 32x32 (img origin oy, ox) ----
    {
        float2 acc[4];
        int bidx[4];
#pragma unroll
        for (int k = 0; k < 4; ++k) {
            int p = tid + k * 256;
            int py = p >> 5, px = p & 31;
            bidx[k] = py * 34 + px;
            acc[k] = make_float2(0.f, 0.f);
        }
#pragma unroll
        for (int ci = 0; ci < 4; ++ci) {
            const float2* Tci = BUF + ci * 1156;
#pragma unroll
            for (int tap = 0; tap < 9; ++tap) {
                float2 w = Wc[ci * 9 + tap];
                int off = (tap / 3) * 34 + tap % 3;
#pragma unroll
                for (int k = 0; k < 4; ++k) {
                    float2 v = Tci[bidx[k] + off];
                    acc[k].x += v.x*w.x - v.y*w.y;
                    acc[k].y += v.x*w.y + v.y*w.x;
                }
            }
        }
        float2* ob = out + (size_t)b * IMG;
#pragma unroll
        for (int k = 0; k < 4; ++k) {
            int p = tid + k * 256;
            int py = p >> 5, px = p & 31;
            int gidx = (oy + py) * 256 + (ox + px);
            float2 v = acc[k];
            if (!ADJ) {
                float tr = thr[b * IMG + gidx], ti = thi[b * IMG + gidx];
                v = make_float2(v.x * tr - v.y * ti, v.x * ti + v.y * tr);
            }
            ob[gidx] = v;
        }
    }
}

// fft2 pass 1: ifftshift on read, forward FFT along x.
__global__ void fft_row_fwd(const int* __restrict__ ep, int iter) {
    if (iter >= get_K(ep)) return;
    __shared__ float2 s[256];
    __shared__ float2 tw[128];
    int b = blockIdx.y, y = blockIdx.x, t = threadIdx.x;
    build_tw(tw, t, -1.0f);
    const float2* irow = g_FB + (b * 256 + (y ^ 128)) * 256;
#pragma unroll
    for (int k = 0; k < 2; ++k) {
        int p = t + k * 128;
        s[rev8(p)] = irow[p ^ 128];
    }
    __syncthreads();
    fft256_ip(s, tw, t);
    float2* orow = g_FA + (b * 256 + y) * 256;
    orow[t]       = s[t];
    orow[t + 128] = s[t + 128];
}

// fft2 pass 2: tiled column forward FFT, crop to 127x127, accumulate into x.
__global__ void fft_col_fwd_accum(const int* __restrict__ ep, int iter) {
    if (iter >= get_K(ep)) return;
    extern __shared__ float2 csm[];
    float2* s  = csm;
    float2* tw = csm + 256 * 32;
    int b  = blockIdx.y;
    int tx = threadIdx.x, ty = threadIdx.y;
    int tid = ty * 32 + tx;
    int x = blockIdx.x * 32 + tx;
    build_tw(tw, tid, -1.0f);
    for (int r = ty; r < 256; r += 8)
        s[rev8(r) * 32 + tx] = g_FA[(b * 256 + r) * 256 + x];
    __syncthreads();
#pragma unroll
    for (int st = 1; st <= 8; ++st) {
        int mh = 1 << (st - 1);
#pragma unroll
        for (int k = 0; k < 16; ++k) {
            int i   = ty * 16 + k;
            int idx = ((i >> (st - 1)) << st) | (i & (mh - 1));
            int twi = (i & (mh - 1)) << (8 - st);
            float2 w = tw[twi];
            float2 u = s[idx * 32 + tx];
            float2 v = s[(idx + mh) * 32 + tx];
            float vr = v.x * w.x - v.y * w.y;
            float vi = v.x * w.y + v.y * w.x;
            s[idx * 32 + tx]        = make_float2(u.x + vr, u.y + vi);
            s[(idx + mh) * 32 + tx] = make_float2(u.x - vr, u.y - vi);
        }
        __syncthreads();
    }
    if (x < 127) {
        for (int r = ty; r < 127; r += 8)
            g_x[b * NN + r * 127 + x] += s[r * 32 + tx].x;
    }
}

// Final residual norm: partial sums of r^2 and f^2.
__global__ void norm_partial(const float* __restrict__ f, const float* __restrict__ kA) {
    __shared__ float sr_s[256], sf_s[256];
    float sr = 0.0f, sf = 0.0f;
    for (int idx = blockIdx.x * 256 + threadIdx.x; idx < NB * NN; idx += 256 * 256) {
        int b = idx / NN;
        int p = idx - b * NN;
        int y = p / 127, x = p - y * 127;
        const float* ka = kA + b * 9;
        const float* xb = g_x + b * NN;
        float s = 0.0f;
        if (y > 0) {
            if (x > 0)   s += ka[0] * xb[p - 128];
            s += ka[1] * xb[p - 127];
            if (x < 126) s += ka[2] * xb[p - 126];
        }
        if (x > 0)   s += ka[3] * xb[p - 1];
        s += ka[4] * xb[p];
        if (x < 126) s += ka[5] * xb[p + 1];
        if (y < 126) {
            if (x > 0)   s += ka[6] * xb[p + 126];
            s += ka[7] * xb[p + 127];
            if (x < 126) s += ka[8] * xb[p + 128];
        }
        float fv = f[idx];
        float rv = fv - s;
        sr += rv * rv;
        sf += fv * fv;
    }
    sr_s[threadIdx.x] = sr;
    sf_s[threadIdx.x] = sf;
    __syncthreads();
    for (int o = 128; o > 0; o >>= 1) {
        if (threadIdx.x < o) {
            sr_s[threadIdx.x] += sr_s[threadIdx.x + o];
            sf_s[threadIdx.x] += sf_s[threadIdx.x + o];
        }
        __syncthreads();
    }
    if (threadIdx.x == 0) g_part[blockIdx.x] = make_float2(sr_s[0], sf_s[0]);
}

__global__ void norm_final(float* __restrict__ out) {
    __shared__ float sr_s[256], sf_s[256];
    float2 v = g_part[threadIdx.x];
    sr_s[threadIdx.x] = v.x;
    sf_s[threadIdx.x] = v.y;
    __syncthreads();
    for (int o = 128; o > 0; o >>= 1) {
        if (threadIdx.x < o) {
            sr_s[threadIdx.x] += sr_s[threadIdx.x + o];
            sf_s[threadIdx.x] += sf_s[threadIdx.x + o];
        }
        __syncthreads();
    }
    if (threadIdx.x == 0) out[0] = sqrtf(sr_s[0] / sf_s[0]);
}

// ---------------- launch ------------------------------------------------------
extern "C" void kernel_launch(void* const* d_in, const int* in_sizes, int n_in,
                              void* d_out, int out_size) {
    (void)in_sizes; (void)n_in; (void)out_size;
    const float* f   = (const float*)d_in[0];
    const float* kA  = (const float*)d_in[1];
    const float* w1r = (const float*)d_in[2];
    const float* w1i = (const float*)d_in[3];
    const float* w2r = (const float*)d_in[4];
    const float* w2i = (const float*)d_in[5];
    const float* w3r = (const float*)d_in[6];
    const float* w3i = (const float*)d_in[7];
    const float* thr = (const float*)d_in[8];
    const float* thi = (const float*)d_in[9];
    const int*   ep  = (const int*)d_in[10];
    float* out = (float*)d_out;

    void *pFA = nullptr, *pFB = nullptr;
    cudaGetSymbolAddress(&pFA, g_FA);
    cudaGetSymbolAddress(&pFB, g_FB);

    const int JSM = 2 * NN * 4;                 // 129032 B
    const int CSM = 256 * 32 * 8 + 128 * 8;     // 66560 B
    const int FSM = (5184 + 4624 + 216) * 8;    // 80192 B
    cudaFuncSetAttribute(jacobi_kernel, cudaFuncAttributeMaxDynamicSharedMemorySize, JSM);
    cudaFuncSetAttribute(fft_col_inv, cudaFuncAttributeMaxDynamicSharedMemorySize, CSM);
    cudaFuncSetAttribute(fft_col_fwd_accum, cudaFuncAttributeMaxDynamicSharedMemorySize, CSM);
    cudaFuncSetAttribute(fused_stack<false>, cudaFuncAttributeMaxDynamicSharedMemorySize, FSM);
    cudaFuncSetAttribute(fused_stack<true>,  cudaFuncAttributeMaxDynamicSharedMemorySize, FSM);

    zero_x_kernel<<<(NB * NN + 255) / 256, 256>>>();

    for (int it = 0; it < 3; ++it) {
        jacobi_kernel<<<NB, 512, JSM>>>(f, kA, ep, it);
        fft_row_expand<<<dim3(256, NB), 128>>>(ep, it);
        fft_col_inv<<<dim3(8, NB), dim3(32, 8), CSM>>>(ep, it);
        fused_stack<false><<<dim3(8, 8, NB), 256, FSM>>>(
            (const float2*)pFB, (float2*)pFA,
            w1r, w1i, w2r, w2i, w3r, w3i, thr, thi, ep, it);
        fused_stack<true><<<dim3(8, 8, NB), 256, FSM>>>(
            (const float2*)pFA, (float2*)pFB,
            w1r, w1i, w2r, w2i, w3r, w3i, nullptr, nullptr, ep, it);
        fft_row_fwd<<<dim3(256, NB), 128>>>(ep, it);
        fft_col_fwd_accum<<<dim3(4, NB), dim3(32, 8), CSM>>>(ep, it);
    }

    norm_partial<<<256, 256>>>(f, kA);
    norm_final<<<1, 256>>>(out);
}

// round 3
// speedup vs baseline: 1.2520x; 1.1238x over previous
#include <cuda_runtime.h>
#include <math.h>

#define NB   16
#define NI   127
#define NN   16129      // 127*127
#define IMG  65536      // 256*256

// ---------------- scratch (static device globals) ----------------------------
static __device__ float  g_x[NB * NN];
static __device__ float  g_r[NB * NN];
static __device__ float2 g_FA[NB * IMG];
static __device__ float2 g_FB[NB * IMG];
static __device__ float2 g_part[256];

// ---------------- helpers ----------------------------------------------------
__device__ __forceinline__ int get_K(const int* ep) {
    int ei = *ep;
    int e;
    if (ei > 0 && ei <= 1000000) {
        e = ei;
    } else {
        float ff = __int_as_float(ei);
        e = (ff >= 1.0f && ff <= 1000000.0f) ? (int)ff : 120;
    }
    int K = (e - 1) / 40 + 1;
    if (K > 10) K = 10;
    if (K < 1)  K = 1;
    return K;
}

__device__ __forceinline__ int rev8(int x) { return (int)(__brev((unsigned)x) >> 24); }

__device__ __forceinline__ void build_tw(float2* tw, int tid, float sign) {
    if (tid < 128) {
        float s, c;
        __sincosf(sign * 6.283185307179586f * (float)tid * (1.0f / 256.0f), &s, &c);
        tw[tid] = make_float2(c, s);
    }
}

// In-place 256-pt DIT FFT over bit-reversed-loaded data; 128 threads, 1 bfly each.
__device__ __forceinline__ void fft256_ip(float2* s, const float2* tw, int t) {
#pragma unroll
    for (int st = 1; st <= 8; ++st) {
        int mh  = 1 << (st - 1);
        int idx = ((t >> (st - 1)) << st) | (t & (mh - 1));
        int twi = (t & (mh - 1)) << (8 - st);
        float2 w = tw[twi];
        float2 u = s[idx];
        float2 v = s[idx + mh];
        float vr = v.x * w.x - v.y * w.y;
        float vi = v.x * w.y + v.y * w.x;
        s[idx]      = make_float2(u.x + vr, u.y + vi);
        s[idx + mh] = make_float2(u.x - vr, u.y - vi);
        __syncthreads();
    }
}

// ---------------- kernels ----------------------------------------------------
__global__ void zero_x_kernel() {
    int i = blockIdx.x * blockDim.x + threadIdx.x;
    if (i < NB * NN) g_x[i] = 0.0f;
}

// One CTA per sample, 1024 threads: 20 Jacobi sweeps in smem, write x & r=f-Ax.
// tx = column (0..126), ty = row-strip (0..7), 16 rows each.
__global__ void __launch_bounds__(1024, 1)
jacobi_kernel(const float* __restrict__ f, const float* __restrict__ kA,
              const int* __restrict__ ep, int iter) {
    if (iter >= get_K(ep)) return;
    extern __shared__ float smem[];
    float* xs0 = smem;
    float* xs1 = smem + NN;
    int b  = blockIdx.x;
    int t  = threadIdx.x;
    int tx = t & 127;
    int ty = t >> 7;                        // 0..7
    const float* ka = kA + b * 9;
    float k0 = ka[0], k1 = ka[1], k2 = ka[2], k3 = ka[3], k4 = ka[4];
    float k5 = ka[5], k6 = ka[6], k7 = ka[7], k8 = ka[8];
    float tau = 0.5f / k4;

    for (int i = t; i < NN; i += 1024) xs0[i] = g_x[b * NN + i];
    __syncthreads();

    int y0 = ty * 16;
    int y1 = min(127, y0 + 16);

    float freg[16];
    if (tx < 127) {
        for (int i = 0; i < 16; ++i) {
            int y = y0 + i;
            if (y < y1) freg[i] = f[b * NN + y * 127 + tx];
        }
    }

    float* cur = xs0;
    float* nxt = xs1;
    for (int it = 0; it < 20; ++it) {
        if (tx < 127) {
            float am, a0, ap, bm, b0, bp;
            if (y0 > 0) {
                int r_ = (y0 - 1) * 127;
                am = (tx > 0)   ? cur[r_ + tx - 1] : 0.0f;
                a0 = cur[r_ + tx];
                ap = (tx < 126) ? cur[r_ + tx + 1] : 0.0f;
            } else { am = a0 = ap = 0.0f; }
            {
                int r_ = y0 * 127;
                bm = (tx > 0)   ? cur[r_ + tx - 1] : 0.0f;
                b0 = cur[r_ + tx];
                bp = (tx < 126) ? cur[r_ + tx + 1] : 0.0f;
            }
            for (int i = 0; i < 16; ++i) {
                int y = y0 + i;
                if (y >= y1) break;
                float cm, c0, cp;
                if (y + 1 < 127) {
                    int r_ = (y + 1) * 127;
                    cm = (tx > 0)   ? cur[r_ + tx - 1] : 0.0f;
                    c0 = cur[r_ + tx];
                    cp = (tx < 126) ? cur[r_ + tx + 1] : 0.0f;
                } else { cm = c0 = cp = 0.0f; }
                float ax = k0 * am + k1 * a0 + k2 * ap
                         + k3 * bm + k4 * b0 + k5 * bp
                         + k6 * cm + k7 * c0 + k8 * cp;
                nxt[y * 127 + tx] = b0 + tau * (freg[i] - ax);
                am = bm; a0 = b0; ap = bp;
                bm = cm; b0 = c0; bp = cp;
            }
        }
        __syncthreads();
        float* tswap = cur; cur = nxt; nxt = tswap;
    }

    if (tx < 127) {
        float am, a0, ap, bm, b0, bp;
        if (y0 > 0) {
            int r_ = (y0 - 1) * 127;
            am = (tx > 0)   ? cur[r_ + tx - 1] : 0.0f;
            a0 = cur[r_ + tx];
            ap = (tx < 126) ? cur[r_ + tx + 1] : 0.0f;
        } else { am = a0 = ap = 0.0f; }
        {
            int r_ = y0 * 127;
            bm = (tx > 0)   ? cur[r_ + tx - 1] : 0.0f;
            b0 = cur[r_ + tx];
            bp = (tx < 126) ? cur[r_ + tx + 1] : 0.0f;
        }
        for (int i = 0; i < 16; ++i) {
            int y = y0 + i;
            if (y >= y1) break;
            float cm, c0, cp;
            if (y + 1 < 127) {
                int r_ = (y + 1) * 127;
                cm = (tx > 0)   ? cur[r_ + tx - 1] : 0.0f;
                c0 = cur[r_ + tx];
                cp = (tx < 126) ? cur[r_ + tx + 1] : 0.0f;
            } else { cm = c0 = cp = 0.0f; }
            float ax = k0 * am + k1 * a0 + k2 * ap
                     + k3 * bm + k4 * b0 + k5 * bp
                     + k6 * cm + k7 * c0 + k8 * cp;
            int p = y * 127 + tx;
            g_x[b * NN + p] = b0;
            g_r[b * NN + p] = freg[i] - ax;
            am = bm; a0 = b0; ap = bp;
            bm = cm; b0 = c0; bp = cp;
        }
    }
}

// ifft2 pass 1 using odd symmetry: only rows 1..127 FFT'd; row 256-y = -row y.
__global__ void fft_row_expand(const int* __restrict__ ep, int iter) {
    if (iter >= get_K(ep)) return;
    __shared__ float2 s[256];
    __shared__ float2 tw[128];
    int b = blockIdx.y, y = blockIdx.x + 1, t = threadIdx.x;   // y in 1..127
    build_tw(tw, t, 1.0f);
    const float* rrow = g_r + (b * NN + (y - 1) * 127);
#pragma unroll
    for (int k = 0; k < 2; ++k) {
        int p = t + k * 128;
        float v = 0.0f;
        if (p >= 1 && p <= 127)  v =  rrow[p - 1];
        else if (p >= 129)       v = -rrow[255 - p];
        s[rev8(p)] = make_float2(v, 0.0f);
    }
    __syncthreads();
    fft256_ip(s, tw, t);
    float2* base = g_FA + (size_t)b * IMG;
    float2 v0 = s[t], v1 = s[t + 128];
    base[y * 256 + t]               = v0;
    base[y * 256 + t + 128]         = v1;
    base[(256 - y) * 256 + t]       = make_float2(-v0.x, -v0.y);
    base[(256 - y) * 256 + t + 128] = make_float2(-v1.x, -v1.y);
    if (y == 1) {   // zero rows 0 and 128
        base[t]             = make_float2(0.f, 0.f);
        base[t + 128]       = make_float2(0.f, 0.f);
        base[128 * 256 + t]       = make_float2(0.f, 0.f);
        base[128 * 256 + t + 128] = make_float2(0.f, 0.f);
    }
}

// ifft2 pass 2: tiled column FFT (32 cols/block), scale, write with fftshift.
__global__ void fft_col_inv(const int* __restrict__ ep, int iter) {
    if (iter >= get_K(ep)) return;
    extern __shared__ float2 csm[];
    float2* s  = csm;
    float2* tw = csm + 256 * 32;
    int b  = blockIdx.y;
    int tx = threadIdx.x, ty = threadIdx.y;
    int tid = ty * 32 + tx;
    int x = blockIdx.x * 32 + tx;
    build_tw(tw, tid, 1.0f);
    for (int r = ty; r < 256; r += 8)
        s[rev8(r) * 32 + tx] = g_FA[(b * 256 + r) * 256 + x];
    __syncthreads();
#pragma unroll
    for (int st = 1; st <= 8; ++st) {
        int mh = 1 << (st - 1);
#pragma unroll
        for (int k = 0; k < 16; ++k) {
            int i   = ty * 16 + k;
            int idx = ((i >> (st - 1)) << st) | (i & (mh - 1));
            int twi = (i & (mh - 1)) << (8 - st);
            float2 w = tw[twi];
            float2 u = s[idx * 32 + tx];
            float2 v = s[(idx + mh) * 32 + tx];
            float vr = v.x * w.x - v.y * w.y;
            float vi = v.x * w.y + v.y * w.x;
            s[idx * 32 + tx]        = make_float2(u.x + vr, u.y + vi);
            s[(idx + mh) * 32 + tx] = make_float2(u.x - vr, u.y - vi);
        }
        __syncthreads();
    }
    const float sc = 1.0f / 65536.0f;
    int xo = x ^ 128;
    for (int r = ty; r < 256; r += 8) {
        float2 v = s[r * 32 + tx];
        g_FB[(b * 256 + (r ^ 128)) * 256 + xo] = make_float2(v.x * sc, v.y * sc);
    }
}

// Fused 3-conv stack, 512 threads: in(1ch)->4->4->1, 32x32 tile, halo 3.
template <bool ADJ>
__global__ void __launch_bounds__(512, 2)
fused_stack(const float2* __restrict__ in, float2* __restrict__ out,
            const float* __restrict__ w1r, const float* __restrict__ w1i,
            const float* __restrict__ w2r, const float* __restrict__ w2i,
            const float* __restrict__ w3r, const float* __restrict__ w3i,
            const float* __restrict__ thr, const float* __restrict__ thi,
            const int* __restrict__ ep, int iter) {
    if (iter >= get_K(ep)) return;
    extern __shared__ float2 sm[];
    float2* T1  = sm;                 // 4 * 36*36 = 5184
    float2* BUF = sm + 5184;          // max(38*38, 4*34*34) = 4624
    float2* Wa  = sm + 5184 + 4624;   // [9][4]
    float2* Wb  = Wa + 36;            // [4][9][4]
    float2* Wc  = Wa + 180;           // [4][9]

    int b   = blockIdx.z;
    int ox  = blockIdx.x * 32;
    int oy  = blockIdx.y * 32;
    int tid = threadIdx.x;

    // ---- weights ----
    if (tid < 216) {
        if (tid < 36) {
            int tap = tid >> 2, co = tid & 3;
            if (!ADJ) {
                int j = (b * 4 + co) * 9 + tap;
                Wa[tid] = make_float2(w1r[j], w1i[j]);
            } else {
                int tt = (tap % 3) * 3 + tap / 3;
                int j = (b * 4 + co) * 9 + tt;
                Wa[tid] = make_float2(w3r[j], -w3i[j]);
            }
        } else if (tid < 180) {
            int u = tid - 36;
            int ci = u / 36, tap = (u % 36) >> 2, co = u & 3;
            if (!ADJ) {
                int j = ((b * 4 + co) * 4 + ci) * 9 + tap;
                Wb[u] = make_float2(w2r[j], w2i[j]);
            } else {
                int tt = (tap % 3) * 3 + tap / 3;
                int j = ((b * 4 + ci) * 4 + co) * 9 + tt;
                Wb[u] = make_float2(w2r[j], -w2i[j]);
            }
        } else {
            int u = tid - 180;
            int ci = u / 9, tap = u % 9;
            if (!ADJ) {
                int j = (b * 4 + ci) * 9 + tap;
                Wc[u] = make_float2(w3r[j], w3i[j]);
            } else {
                int tt = (tap % 3) * 3 + tap / 3;
                int j = (b * 4 + ci) * 9 + tt;
                Wc[u] = make_float2(w1r[j], -w1i[j]);
            }
        }
    }

    // ---- input tile 38x38, zero pad ----
    const float2* inb = in + (size_t)b * IMG;
    for (int i = tid; i < 38 * 38; i += 512) {
        int iy = i / 38, ix = i % 38;
        int gy = oy - 3 + iy, gx = ox - 3 + ix;
        float2 v = make_float2(0.0f, 0.0f);
        if ((unsigned)gy < 256u && (unsigned)gx < 256u) v = inb[gy * 256 + gx];
        BUF[i] = v;
    }
    __syncthreads();

    // ---- stage 1: 1 -> 4, 36x36 region ----
    for (int p = tid; p < 1296; p += 512) {
        int py = p / 36, px = p % 36;
        int gy = oy - 2 + py, gx = ox - 2 + px;
        float2 a0 = make_float2(0.f, 0.f), a1 = a0, a2 = a0, a3 = a0;
        if ((unsigned)gy < 256u && (unsigned)gx < 256u) {
            int base = py * 38 + px;
#pragma unroll
            for (int tap = 0; tap < 9; ++tap) {
                float2 v = BUF[base + (tap / 3) * 38 + tap % 3];
                float2 w;
                w = Wa[tap * 4 + 0]; a0.x += v.x*w.x - v.y*w.y; a0.y += v.x*w.y + v.y*w.x;
                w = Wa[tap * 4 + 1]; a1.x += v.x*w.x - v.y*w.y; a1.y += v.x*w.y + v.y*w.x;
                w = Wa[tap * 4 + 2]; a2.x += v.x*w.x - v.y*w.y; a2.y += v.x*w.y + v.y*w.x;
                w = Wa[tap * 4 + 3]; a3.x += v.x*w.x - v.y*w.y; a3.y += v.x*w.y + v.y*w.x;
            }
        }
        T1[0 * 1296 + p] = a0;
        T1[1 * 1296 + p] = a1;
        T1[2 * 1296 + p] = a2;
        T1[3 * 1296 + p] = a3;
    }
    __syncthreads();

    // ---- stage 2: 4 -> 4, 34x34 region -> BUF ----
    {
        float2 acc[3][4];
        int bidx[3];
        bool val[3];
#pragma unroll
        for (int k = 0; k < 3; ++k) {
            int p = tid + k * 512;
            val[k] = p < 1156;
            int py = p / 34, px = p % 34;
            bidx[k] = py * 36 + px;
#pragma unroll
            for (int c = 0; c < 4; ++c) acc[k][c] = make_float2(0.f, 0.f);
        }
#pragma unroll
        for (int ci = 0; ci < 4; ++ci) {
            const float2* Tci = T1 + ci * 1296;
#pragma unroll
            for (int tap = 0; tap < 9; ++tap) {
                float2 w0 = Wb[(ci * 9 + tap) * 4 + 0];
                float2 w1 = Wb[(ci * 9 + tap) * 4 + 1];
                float2 w2 = Wb[(ci * 9 + tap) * 4 + 2];
                float2 w3 = Wb[(ci * 9 + tap) * 4 + 3];
                int off = (tap / 3) * 36 + tap % 3;
#pragma unroll
                for (int k = 0; k < 3; ++k) {
                    if (val[k]) {
                        float2 v = Tci[bidx[k] + off];
                        acc[k][0].x += v.x*w0.x - v.y*w0.y; acc[k][0].y += v.x*w0.y + v.y*w0.x;
                        acc[k][1].x += v.x*w1.x - v.y*w1.y; acc[k][1].y += v.x*w1.y + v.y*w1.x;
                        acc[k][2].x += v.x*w2.x - v.y*w2.y; acc[k][2].y += v.x*w2.y + v.y*w2.x;
                        acc[k][3].x += v.x*w3.x - v.y*w3.y; acc[k][3].y += v.x*w3.y + v.y*w3.x;
                    }
                }
            }
        }
        __syncthreads();
#pragma unroll
        for (int k = 0; k < 3; ++k) {
            if (val[k]) {
                int p = tid + k * 512;
                int py = p / 34, px = p % 34;
                int gy = oy - 1 + py, gx = ox - 1 + px;
                bool inb2 = ((unsigned)gy < 256u) && ((unsigned)gx < 256u);
#pragma unroll
                for (int c = 0; c < 4; ++c)
                    BUF[c * 1156 + p] = inb2 ? acc[k][c] : make_float2(0.f, 0.f);
            }
        }
    }
    __syncthreads();

    // ---- stage 3: 4 -> 1, 32x32 region ----
    {
        float2 acc[2];
        int bidx[2];
#pragma unroll
        for (int k = 0; k < 2; ++k) {
            int p = tid + k * 512;
            int py = p >> 5, px = p & 31;
            bidx[k] = py * 34 + px;
            acc[k] = make_float2(0.f, 0.f);
        }
#pragma unroll
        for (int ci = 0; ci < 4; ++ci) {
            const float2* Tci = BUF + ci * 1156;
#pragma unroll
            for (int tap = 0; tap < 9; ++tap) {
                float2 w = Wc[ci * 9 + tap];
                int off = (tap / 3) * 34 + tap % 3;
#pragma unroll
                for (int k = 0; k < 2; ++k) {
                    float2 v = Tci[bidx[k] + off];
                    acc[k].x += v.x*w.x - v.y*w.y;
                    acc[k].y += v.x*w.y + v.y*w.x;
                }
            }
        }
        float2* ob = out + (size_t)b * IMG;
#pragma unroll
        for (int k = 0; k < 2; ++k) {
            int p = tid + k * 512;
            int py = p >> 5, px = p & 31;
            int gidx = (oy + py) * 256 + (ox + px);
            float2 v = acc[k];
            if (!ADJ) {
                float tr = thr[b * IMG + gidx], ti = thi[b * IMG + gidx];
                v = make_float2(v.x * tr - v.y * ti, v.x * ti + v.y * tr);
            }
            ob[gidx] = v;
        }
    }
}

// fft2 pass 1: ifftshift on read, forward FFT along x.
__global__ void fft_row_fwd(const int* __restrict__ ep, int iter) {
    if (iter >= get_K(ep)) return;
    __shared__ float2 s[256];
    __shared__ float2 tw[128];
    int b = blockIdx.y, y = blockIdx.x, t = threadIdx.x;
    build_tw(tw, t, -1.0f);
    const float2* irow = g_FB + (b * 256 + (y ^ 128)) * 256;
#pragma unroll
    for (int k = 0; k < 2; ++k) {
        int p = t + k * 128;
        s[rev8(p)] = irow[p ^ 128];
    }
    __syncthreads();
    fft256_ip(s, tw, t);
    float2* orow = g_FA + (b * 256 + y) * 256;
    orow[t]       = s[t];
    orow[t + 128] = s[t + 128];
}

// fft2 pass 2: tiled column forward FFT, crop 127x127, accumulate into x.
__global__ void fft_col_fwd_accum(const int* __restrict__ ep, int iter) {
    if (iter >= get_K(ep)) return;
    extern __shared__ float2 csm[];
    float2* s  = csm;
    float2* tw = csm + 256 * 32;
    int b  = blockIdx.y;
    int tx = threadIdx.x, ty = threadIdx.y;
    int tid = ty * 32 + tx;
    int x = blockIdx.x * 32 + tx;
    build_tw(tw, tid, -1.0f);
    for (int r = ty; r < 256; r += 8)
        s[rev8(r) * 32 + tx] = g_FA[(b * 256 + r) * 256 + x];
    __syncthreads();
#pragma unroll
    for (int st = 1; st <= 8; ++st) {
        int mh = 1 << (st - 1);
#pragma unroll
        for (int k = 0; k < 16; ++k) {
            int i   = ty * 16 + k;
            int idx = ((i >> (st - 1)) << st) | (i & (mh - 1));
            int twi = (i & (mh - 1)) << (8 - st);
            float2 w = tw[twi];
            float2 u = s[idx * 32 + tx];
            float2 v = s[(idx + mh) * 32 + tx];
            float vr = v.x * w.x - v.y * w.y;
            float vi = v.x * w.y + v.y * w.x;
            s[idx * 32 + tx]        = make_float2(u.x + vr, u.y + vi);
            s[(idx + mh) * 32 + tx] = make_float2(u.x - vr, u.y - vi);
        }
        __syncthreads();
    }
    if (x < 127) {
        for (int r = ty; r < 127; r += 8)
            g_x[b * NN + r * 127 + x] += s[r * 32 + tx].x;
    }
}

// Final residual norm.
__global__ void norm_partial(const float* __restrict__ f, const float* __restrict__ kA) {
    __shared__ float sr_s[256], sf_s[256];
    float sr = 0.0f, sf = 0.0f;
    for (int idx = blockIdx.x * 256 + threadIdx.x; idx < NB * NN; idx += 256 * 256) {
        int b = idx / NN;
        int p = idx - b * NN;
        int y = p / 127, x = p - y * 127;
        const float* ka = kA + b * 9;
        const float* xb = g_x + b * NN;
        float s = 0.0f;
        if (y > 0) {
            if (x > 0)   s += ka[0] * xb[p - 128];
            s += ka[1] * xb[p - 127];
            if (x < 126) s += ka[2] * xb[p - 126];
        }
        if (x > 0)   s += ka[3] * xb[p - 1];
        s += ka[4] * xb[p];
        if (x < 126) s += ka[5] * xb[p + 1];
        if (y < 126) {
            if (x > 0)   s += ka[6] * xb[p + 126];
            s += ka[7] * xb[p + 127];
            if (x < 126) s += ka[8] * xb[p + 128];
        }
        float fv = f[idx];
        float rv = fv - s;
        sr += rv * rv;
        sf += fv * fv;
    }
    sr_s[threadIdx.x] = sr;
    sf_s[threadIdx.x] = sf;
    __syncthreads();
    for (int o = 128; o > 0; o >>= 1) {
        if (threadIdx.x < o) {
            sr_s[threadIdx.x] += sr_s[threadIdx.x + o];
            sf_s[threadIdx.x] += sf_s[threadIdx.x + o];
        }
        __syncthreads();
    }
    if (threadIdx.x == 0) g_part[blockIdx.x] = make_float2(sr_s[0], sf_s[0]);
}

__global__ void norm_final(float* __restrict__ out) {
    __shared__ float sr_s[256], sf_s[256];
    float2 v = g_part[threadIdx.x];
    sr_s[threadIdx.x] = v.x;
    sf_s[threadIdx.x] = v.y;
    __syncthreads();
    for (int o = 128; o > 0; o >>= 1) {
        if (threadIdx.x < o) {
            sr_s[threadIdx.x] += sr_s[threadIdx.x + o];
            sf_s[threadIdx.x] += sf_s[threadIdx.x + o];
        }
        __syncthreads();
    }
    if (threadIdx.x == 0) out[0] = sqrtf(sr_s[0] / sf_s[0]);
}

// ---------------- launch ------------------------------------------------------
extern "C" void kernel_launch(void* const* d_in, const int* in_sizes, int n_in,
                              void* d_out, int out_size) {
    (void)in_sizes; (void)n_in; (void)out_size;
    const float* f   = (const float*)d_in[0];
    const float* kA  = (const float*)d_in[1];
    const float* w1r = (const float*)d_in[2];
    const float* w1i = (const float*)d_in[3];
    const float* w2r = (const float*)d_in[4];
    const float* w2i = (const float*)d_in[5];
    const float* w3r = (const float*)d_in[6];
    const float* w3i = (const float*)d_in[7];
    const float* thr = (const float*)d_in[8];
    const float* thi = (const float*)d_in[9];
    const int*   ep  = (const int*)d_in[10];
    float* out = (float*)d_out;

    void *pFA = nullptr, *pFB = nullptr;
    cudaGetSymbolAddress(&pFA, g_FA);
    cudaGetSymbolAddress(&pFB, g_FB);

    const int JSM = 2 * NN * 4;                 // 129032 B
    const int CSM = 256 * 32 * 8 + 128 * 8;     // 66560 B
    const int FSM = (5184 + 4624 + 216) * 8;    // 80192 B
    cudaFuncSetAttribute(jacobi_kernel, cudaFuncAttributeMaxDynamicSharedMemorySize, JSM);
    cudaFuncSetAttribute(fft_col_inv, cudaFuncAttributeMaxDynamicSharedMemorySize, CSM);
    cudaFuncSetAttribute(fft_col_fwd_accum, cudaFuncAttributeMaxDynamicSharedMemorySize, CSM);
    cudaFuncSetAttribute(fused_stack<false>, cudaFuncAttributeMaxDynamicSharedMemorySize, FSM);
    cudaFuncSetAttribute(fused_stack<true>,  cudaFuncAttributeMaxDynamicSharedMemorySize, FSM);

    zero_x_kernel<<<(NB * NN + 255) / 256, 256>>>();

    for (int it = 0; it < 3; ++it) {
        jacobi_kernel<<<NB, 1024, JSM>>>(f, kA, ep, it);
        fft_row_expand<<<dim3(127, NB), 128>>>(ep, it);
        fft_col_inv<<<dim3(8, NB), dim3(32, 8), CSM>>>(ep, it);
        fused_stack<false><<<dim3(8, 8, NB), 512, FSM>>>(
            (const float2*)pFB, (float2*)pFA,
            w1r, w1i, w2r, w2i, w3r, w3i, thr, thi, ep, it);
        fused_stack<true><<<dim3(8, 8, NB), 512, FSM>>>(
            (const float2*)pFA, (float2*)pFB,
            w1r, w1i, w2r, w2i, w3r, w3i, nullptr, nullptr, ep, it);
        fft_row_fwd<<<dim3(256, NB), 128>>>(ep, it);
        fft_col_fwd_accum<<<dim3(4, NB), dim3(32, 8), CSM>>>(ep, it);
    }

    norm_partial<<<256, 256>>>(f, kA);
    norm_final<<<1, 256>>>(out);
}

// round 5
// speedup vs baseline: 1.2948x; 1.0342x over previous
#include <cuda_runtime.h>
#include <math.h>

#define NB   16
#define NI   127
#define NN   16129      // 127*127
#define IMG  65536      // 256*256
#define TS   32
#define HL   6
#define LT   44         // TS + 2*HL

// ---------------- scratch (static device globals) ----------------------------
static __device__ float  g_x[NB * NN];
static __device__ float  g_r[NB * NN];
static __device__ float2 g_FA[NB * IMG];
static __device__ float2 g_FB[NB * IMG];
static __device__ float2 g_part[256];

// ---------------- helpers ----------------------------------------------------
__device__ __forceinline__ int get_K(const int* ep) {
    int ei = *ep;
    int e;
    if (ei > 0 && ei <= 1000000) {
        e = ei;
    } else {
        float ff = __int_as_float(ei);
        e = (ff >= 1.0f && ff <= 1000000.0f) ? (int)ff : 120;
    }
    int K = (e - 1) / 40 + 1;
    if (K > 10) K = 10;
    if (K < 1)  K = 1;
    return K;
}

__device__ __forceinline__ int rev8(int x) { return (int)(__brev((unsigned)x) >> 24); }

__device__ __forceinline__ void build_tw(float2* tw, int tid, float sign) {
    if (tid < 128) {
        float s, c;
        __sincosf(sign * 6.283185307179586f * (float)tid * (1.0f / 256.0f), &s, &c);
        tw[tid] = make_float2(c, s);
    }
}

// In-place 256-pt DIT FFT (bit-reversed input); 128 threads per row, 1 bfly each.
__device__ __forceinline__ void fft256_ip(float2* s, const float2* tw, int t) {
#pragma unroll
    for (int st = 1; st <= 8; ++st) {
        int mh  = 1 << (st - 1);
        int idx = ((t >> (st - 1)) << st) | (t & (mh - 1));
        int twi = (t & (mh - 1)) << (8 - st);
        float2 w = tw[twi];
        float2 u = s[idx];
        float2 v = s[idx + mh];
        float vr = v.x * w.x - v.y * w.y;
        float vi = v.x * w.y + v.y * w.x;
        s[idx]      = make_float2(u.x + vr, u.y + vi);
        s[idx + mh] = make_float2(u.x - vr, u.y - vi);
        __syncthreads();
    }
}

// ---------------- kernels ----------------------------------------------------
__global__ void zero_x_kernel() {
    int i = blockIdx.x * blockDim.x + threadIdx.x;
    if (i < NB * NN) g_x[i] = 0.0f;
}

// Sweep-chunked Jacobi: 5 sweeps per launch on 44x44 tiles (halo 6).
// final!=0: also emit r = f - A x on the 32x32 interior.
__global__ void __launch_bounds__(256, 4)
jacobi_tile(const float* __restrict__ f, const float* __restrict__ kA,
            const int* __restrict__ ep, int iter, int final_) {
    if (iter >= get_K(ep)) return;
    __shared__ float xs0[LT * LT], xs1[LT * LT], fs[LT * LT];
    int b  = blockIdx.z;
    int ox = blockIdx.x * TS - HL;
    int oy = blockIdx.y * TS - HL;
    int tid = threadIdx.x;
    const float* ka = kA + b * 9;
    float k0 = ka[0], k1 = ka[1], k2 = ka[2], k3 = ka[3], k4 = ka[4];
    float k5 = ka[5], k6 = ka[6], k7 = ka[7], k8 = ka[8];
    float tau = 0.5f / k4;

    for (int i = tid; i < LT * LT; i += 256) {
        int iy = i / LT, ix = i % LT;
        int gy = oy + iy, gx = ox + ix;
        bool in = ((unsigned)gy < 127u) && ((unsigned)gx < 127u);
        xs0[i] = in ? g_x[b * NN + gy * 127 + gx] : 0.0f;
        fs[i]  = in ? f[b * NN + gy * 127 + gx] : 0.0f;
    }
    __syncthreads();

    float* cur = xs0;
    float* nxt = xs1;
#pragma unroll
    for (int s = 0; s < 5; ++s) {
        int a = s + 1;
        for (int i = tid; i < LT * LT; i += 256) {
            int iy = i / LT, ix = i % LT;
            float nv = cur[i];
            if (iy >= a && iy < LT - a && ix >= a && ix < LT - a) {
                int gy = oy + iy, gx = ox + ix;
                if (((unsigned)gy < 127u) && ((unsigned)gx < 127u)) {
                    float ax = k0 * cur[i - LT - 1] + k1 * cur[i - LT] + k2 * cur[i - LT + 1]
                             + k3 * cur[i - 1]      + k4 * cur[i]      + k5 * cur[i + 1]
                             + k6 * cur[i + LT - 1] + k7 * cur[i + LT] + k8 * cur[i + LT + 1];
                    nv = cur[i] + tau * (fs[i] - ax);
                }
            }
            nxt[i] = nv;
        }
        __syncthreads();
        float* tsw = cur; cur = nxt; nxt = tsw;
    }

    for (int p = tid; p < TS * TS; p += 256) {
        int py = p >> 5, px = p & 31;
        int iy = HL + py, ix = HL + px;
        int gy = oy + iy, gx = ox + ix;
        if (((unsigned)gy < 127u) && ((unsigned)gx < 127u)) {
            int i = iy * LT + ix;
            g_x[b * NN + gy * 127 + gx] = cur[i];
            if (final_) {
                float ax = k0 * cur[i - LT - 1] + k1 * cur[i - LT] + k2 * cur[i - LT + 1]
                         + k3 * cur[i - 1]      + k4 * cur[i]      + k5 * cur[i + 1]
                         + k6 * cur[i + LT - 1] + k7 * cur[i + LT] + k8 * cur[i + LT + 1];
                g_r[b * NN + gy * 127 + gx] = fs[i] - ax;
            }
        }
    }
}

// ifft2 pass 1 (odd symmetry): rows 1..127 FFT'd, row 256-y = -row y. 4 rows/block.
__global__ void __launch_bounds__(512)
fft_row_expand(const int* __restrict__ ep, int iter) {
    if (iter >= get_K(ep)) return;
    __shared__ float2 s[4][256];
    __shared__ float2 tw[128];
    int b = blockIdx.y, t = threadIdx.x, ty = threadIdx.y;
    int y = blockIdx.x * 4 + ty + 1;            // 1..128 (128 invalid)
    bool ok = (y <= 127);
    build_tw(tw, ty * 128 + t, 1.0f);
    const float* rrow = g_r + (b * NN + (ok ? (y - 1) : 0) * 127);
#pragma unroll
    for (int k = 0; k < 2; ++k) {
        int p = t + k * 128;
        float v = 0.0f;
        if (ok) {
            if (p >= 1 && p <= 127)  v =  rrow[p - 1];
            else if (p >= 129)       v = -rrow[255 - p];
        }
        s[ty][rev8(p)] = make_float2(v, 0.0f);
    }
    __syncthreads();
    fft256_ip(s[ty], tw, t);
    if (ok) {
        float2* base = g_FA + (size_t)b * IMG;
        float2 v0 = s[ty][t], v1 = s[ty][t + 128];
        base[y * 256 + t]               = v0;
        base[y * 256 + t + 128]         = v1;
        base[(256 - y) * 256 + t]       = make_float2(-v0.x, -v0.y);
        base[(256 - y) * 256 + t + 128] = make_float2(-v1.x, -v1.y);
        if (y == 1) {
            base[t]                   = make_float2(0.f, 0.f);
            base[t + 128]             = make_float2(0.f, 0.f);
            base[128 * 256 + t]       = make_float2(0.f, 0.f);
            base[128 * 256 + t + 128] = make_float2(0.f, 0.f);
        }
    }
}

// ifft2 pass 2: tiled column FFT, 1024 threads (4 bfly/thread), fftshift write.
__global__ void __launch_bounds__(1024)
fft_col_inv(const int* __restrict__ ep, int iter) {
    if (iter >= get_K(ep)) return;
    extern __shared__ float2 csm[];
    float2* s  = csm;
    float2* tw = csm + 256 * 32;
    int b  = blockIdx.y;
    int tx = threadIdx.x, ty = threadIdx.y;     // 32 x 32
    int tid = ty * 32 + tx;
    int x = blockIdx.x * 32 + tx;
    build_tw(tw, tid, 1.0f);
    for (int r = ty; r < 256; r += 32)
        s[rev8(r) * 32 + tx] = g_FA[(b * 256 + r) * 256 + x];
    __syncthreads();
#pragma unroll
    for (int st = 1; st <= 8; ++st) {
        int mh = 1 << (st - 1);
#pragma unroll
        for (int k = 0; k < 4; ++k) {
            int i   = ty * 4 + k;
            int idx = ((i >> (st - 1)) << st) | (i & (mh - 1));
            int twi = (i & (mh - 1)) << (8 - st);
            float2 w = tw[twi];
            float2 u = s[idx * 32 + tx];
            float2 v = s[(idx + mh) * 32 + tx];
            float vr = v.x * w.x - v.y * w.y;
            float vi = v.x * w.y + v.y * w.x;
            s[idx * 32 + tx]        = make_float2(u.x + vr, u.y + vi);
            s[(idx + mh) * 32 + tx] = make_float2(u.x - vr, u.y - vi);
        }
        __syncthreads();
    }
    const float sc = 1.0f / 65536.0f;
    int xo = x ^ 128;
    for (int r = ty; r < 256; r += 32) {
        float2 v = s[r * 32 + tx];
        g_FB[(b * 256 + (r ^ 128)) * 256 + xo] = make_float2(v.x * sc, v.y * sc);
    }
}

// Fused 3-conv stack, 512 threads, smem 55KB (T2 aliases T1).
template <bool ADJ>
__global__ void __launch_bounds__(512, 2)
fused_stack(const float2* __restrict__ in, float2* __restrict__ out,
            const float* __restrict__ w1r, const float* __restrict__ w1i,
            const float* __restrict__ w2r, const float* __restrict__ w2i,
            const float* __restrict__ w3r, const float* __restrict__ w3i,
            const float* __restrict__ thr, const float* __restrict__ thi,
            const int* __restrict__ ep, int iter) {
    if (iter >= get_K(ep)) return;
    extern __shared__ float2 sm[];
    float2* IN = sm;                  // 38*38 = 1444
    float2* T1 = sm + 1444;           // 4*36*36 = 5184 (later reused as T2 4*1156)
    float2* Wa = sm + 1444 + 5184;    // [9][4]
    float2* Wb = Wa + 36;             // [4][9][4]
    float2* Wc = Wa + 180;            // [4][9]

    int b   = blockIdx.z;
    int ox  = blockIdx.x * 32;
    int oy  = blockIdx.y * 32;
    int tid = threadIdx.x;

    if (tid < 216) {
        if (tid < 36) {
            int tap = tid >> 2, co = tid & 3;
            if (!ADJ) {
                int j = (b * 4 + co) * 9 + tap;
                Wa[tid] = make_float2(w1r[j], w1i[j]);
            } else {
                int tt = (tap % 3) * 3 + tap / 3;
                int j = (b * 4 + co) * 9 + tt;
                Wa[tid] = make_float2(w3r[j], -w3i[j]);
            }
        } else if (tid < 180) {
            int u = tid - 36;
            int ci = u / 36, tap = (u % 36) >> 2, co = u & 3;
            if (!ADJ) {
                int j = ((b * 4 + co) * 4 + ci) * 9 + tap;
                Wb[u] = make_float2(w2r[j], w2i[j]);
            } else {
                int tt = (tap % 3) * 3 + tap / 3;
                int j = ((b * 4 + ci) * 4 + co) * 9 + tt;
                Wb[u] = make_float2(w2r[j], -w2i[j]);
            }
        } else {
            int u = tid - 180;
            int ci = u / 9, tap = u % 9;
            if (!ADJ) {
                int j = (b * 4 + ci) * 9 + tap;
                Wc[u] = make_float2(w3r[j], w3i[j]);
            } else {
                int tt = (tap % 3) * 3 + tap / 3;
                int j = (b * 4 + ci) * 9 + tt;
                Wc[u] = make_float2(w1r[j], -w1i[j]);
            }
        }
    }

    const float2* inb = in + (size_t)b * IMG;
    for (int i = tid; i < 38 * 38; i += 512) {
        int iy = i / 38, ix = i % 38;
        int gy = oy - 3 + iy, gx = ox - 3 + ix;
        float2 v = make_float2(0.0f, 0.0f);
        if ((unsigned)gy < 256u && (unsigned)gx < 256u) v = inb[gy * 256 + gx];
        IN[i] = v;
    }
    __syncthreads();

    // stage 1: 1 -> 4 over 36x36
    for (int p = tid; p < 1296; p += 512) {
        int py = p / 36, px = p % 36;
        int gy = oy - 2 + py, gx = ox - 2 + px;
        float2 a0 = make_float2(0.f, 0.f), a1 = a0, a2 = a0, a3 = a0;
        if ((unsigned)gy < 256u && (unsigned)gx < 256u) {
            int base = py * 38 + px;
#pragma unroll
            for (int tap = 0; tap < 9; ++tap) {
                float2 v = IN[base + (tap / 3) * 38 + tap % 3];
                float2 w;
                w = Wa[tap * 4 + 0]; a0.x += v.x*w.x - v.y*w.y; a0.y += v.x*w.y + v.y*w.x;
                w = Wa[tap * 4 + 1]; a1.x += v.x*w.x - v.y*w.y; a1.y += v.x*w.y + v.y*w.x;
                w = Wa[tap * 4 + 2]; a2.x += v.x*w.x - v.y*w.y; a2.y += v.x*w.y + v.y*w.x;
                w = Wa[tap * 4 + 3]; a3.x += v.x*w.x - v.y*w.y; a3.y += v.x*w.y + v.y*w.x;
            }
        }
        T1[0 * 1296 + p] = a0;
        T1[1 * 1296 + p] = a1;
        T1[2 * 1296 + p] = a2;
        T1[3 * 1296 + p] = a3;
    }
    __syncthreads();

    // stage 2: 4 -> 4 over 34x34; accumulate in regs, then write T2 into T1 space
    {
        float2 acc[3][4];
        int bidx[3];
        bool val[3];
#pragma unroll
        for (int k = 0; k < 3; ++k) {
            int p = tid + k * 512;
            val[k] = p < 1156;
            int py = p / 34, px = p % 34;
            bidx[k] = py * 36 + px;
#pragma unroll
            for (int c = 0; c < 4; ++c) acc[k][c] = make_float2(0.f, 0.f);
        }
#pragma unroll
        for (int ci = 0; ci < 4; ++ci) {
            const float2* Tci = T1 + ci * 1296;
#pragma unroll
            for (int tap = 0; tap < 9; ++tap) {
                float2 w0 = Wb[(ci * 9 + tap) * 4 + 0];
                float2 w1 = Wb[(ci * 9 + tap) * 4 + 1];
                float2 w2 = Wb[(ci * 9 + tap) * 4 + 2];
                float2 w3 = Wb[(ci * 9 + tap) * 4 + 3];
                int off = (tap / 3) * 36 + tap % 3;
#pragma unroll
                for (int k = 0; k < 3; ++k) {
                    if (val[k]) {
                        float2 v = Tci[bidx[k] + off];
                        acc[k][0].x += v.x*w0.x - v.y*w0.y; acc[k][0].y += v.x*w0.y + v.y*w0.x;
                        acc[k][1].x += v.x*w1.x - v.y*w1.y; acc[k][1].y += v.x*w1.y + v.y*w1.x;
                        acc[k][2].x += v.x*w2.x - v.y*w2.y; acc[k][2].y += v.x*w2.y + v.y*w2.x;
                        acc[k][3].x += v.x*w3.x - v.y*w3.y; acc[k][3].y += v.x*w3.y + v.y*w3.x;
                    }
                }
            }
        }
        __syncthreads();   // all T1 reads complete; safe to overwrite with T2
#pragma unroll
        for (int k = 0; k < 3; ++k) {
            if (val[k]) {
                int p = tid + k * 512;
                int py = p / 34, px = p % 34;
                int gy = oy - 1 + py, gx = ox - 1 + px;
                bool inb2 = ((unsigned)gy < 256u) && ((unsigned)gx < 256u);
#pragma unroll
                for (int c = 0; c < 4; ++c)
                    T1[c * 1156 + p] = inb2 ? acc[k][c] : make_float2(0.f, 0.f);
            }
        }
    }
    __syncthreads();

    // stage 3: 4 -> 1 over 32x32
    {
        float2 acc[2];
        int bidx[2];
#pragma unroll
        for (int k = 0; k < 2; ++k) {
            int p = tid + k * 512;
            int py = p >> 5, px = p & 31;
            bidx[k] = py * 34 + px;
            acc[k] = make_float2(0.f, 0.f);
        }
#pragma unroll
        for (int ci = 0; ci < 4; ++ci) {
            const float2* Tci = T1 + ci * 1156;
#pragma unroll
            for (int tap = 0; tap < 9; ++tap) {
                float2 w = Wc[ci * 9 + tap];
                int off = (tap / 3) * 34 + tap % 3;
#pragma unroll
                for (int k = 0; k < 2; ++k) {
                    float2 v = Tci[bidx[k] + off];
                    acc[k].x += v.x*w.x - v.y*w.y;
                    acc[k].y += v.x*w.y + v.y*w.x;
                }
            }
        }
        float2* ob = out + (size_t)b * IMG;
#pragma unroll
        for (int k = 0; k < 2; ++k) {
            int p = tid + k * 512;
            int py = p >> 5, px = p & 31;
            int gidx = (oy + py) * 256 + (ox + px);
            float2 v = acc[k];
            if (!ADJ) {
                float tr = thr[b * IMG + gidx], ti = thi[b * IMG + gidx];
                v = make_float2(v.x * tr - v.y * ti, v.x * ti + v.y * tr);
            }
            ob[gidx] = v;
        }
    }
}

// fft2 pass 1: ifftshift on read, forward FFT along x. 4 rows/block.
__global__ void __launch_bounds__(512)
fft_row_fwd(const int* __restrict__ ep, int iter) {
    if (iter >= get_K(ep)) return;
    __shared__ float2 s[4][256];
    __shared__ float2 tw[128];
    int b = blockIdx.y, t = threadIdx.x, ty = threadIdx.y;
    int y = blockIdx.x * 4 + ty;
    build_tw(tw, ty * 128 + t, -1.0f);
    const float2* irow = g_FB + (b * 256 + (y ^ 128)) * 256;
#pragma unroll
    for (int k = 0; k < 2; ++k) {
        int p = t + k * 128;
        s[ty][rev8(p)] = irow[p ^ 128];
    }
    __syncthreads();
    fft256_ip(s[ty], tw, t);
    float2* orow = g_FA + (b * 256 + y) * 256;
    orow[t]       = s[ty][t];
    orow[t + 128] = s[ty][t + 128];
}

// fft2 pass 2: tiled column forward FFT (1024 thr), crop 127x127, accumulate into x.
__global__ void __launch_bounds__(1024)
fft_col_fwd_accum(const int* __restrict__ ep, int iter) {
    if (iter >= get_K(ep)) return;
    extern __shared__ float2 csm[];
    float2* s  = csm;
    float2* tw = csm + 256 * 32;
    int b  = blockIdx.y;
    int tx = threadIdx.x, ty = threadIdx.y;
    int tid = ty * 32 + tx;
    int x = blockIdx.x * 32 + tx;
    build_tw(tw, tid, -1.0f);
    for (int r = ty; r < 256; r += 32)
        s[rev8(r) * 32 + tx] = g_FA[(b * 256 + r) * 256 + x];
    __syncthreads();
#pragma unroll
    for (int st = 1; st <= 8; ++st) {
        int mh = 1 << (st - 1);
#pragma unroll
        for (int k = 0; k < 4; ++k) {
            int i   = ty * 4 + k;
            int idx = ((i >> (st - 1)) << st) | (i & (mh - 1));
            int twi = (i & (mh - 1)) << (8 - st);
            float2 w = tw[twi];
            float2 u = s[idx * 32 + tx];
            float2 v = s[(idx + mh) * 32 + tx];
            float vr = v.x * w.x - v.y * w.y;
            float vi = v.x * w.y + v.y * w.x;
            s[idx * 32 + tx]        = make_float2(u.x + vr, u.y + vi);
            s[(idx + mh) * 32 + tx] = make_float2(u.x - vr, u.y - vi);
        }
        __syncthreads();
    }
    if (x < 127) {
        for (int r = ty; r < 127; r += 32)
            g_x[b * NN + r * 127 + x] += s[r * 32 + tx].x;
    }
}

// Final residual norm.
__global__ void norm_partial(const float* __restrict__ f, const float* __restrict__ kA) {
    __shared__ float sr_s[256], sf_s[256];
    float sr = 0.0f, sf = 0.0f;
    for (int idx = blockIdx.x * 256 + threadIdx.x; idx < NB * NN; idx += 256 * 256) {
        int b = idx / NN;
        int p = idx - b * NN;
        int y = p / 127, x = p - y * 127;
        const float* ka = kA + b * 9;
        const float* xb = g_x + b * NN;
        float s = 0.0f;
        if (y > 0) {
            if (x > 0)   s += ka[0] * xb[p - 128];
            s += ka[1] * xb[p - 127];
            if (x < 126) s += ka[2] * xb[p - 126];
        }
        if (x > 0)   s += ka[3] * xb[p - 1];
        s += ka[4] * xb[p];
        if (x < 126) s += ka[5] * xb[p + 1];
        if (y < 126) {
            if (x > 0)   s += ka[6] * xb[p + 126];
            s += ka[7] * xb[p + 127];
            if (x < 126) s += ka[8] * xb[p + 128];
        }
        float fv = f[idx];
        float rv = fv - s;
        sr += rv * rv;
        sf += fv * fv;
    }
    sr_s[threadIdx.x] = sr;
    sf_s[threadIdx.x] = sf;
    __syncthreads();
    for (int o = 128; o > 0; o >>= 1) {
        if (threadIdx.x < o) {
            sr_s[threadIdx.x] += sr_s[threadIdx.x + o];
            sf_s[threadIdx.x] += sf_s[threadIdx.x + o];
        }
        __syncthreads();
    }
    if (threadIdx.x == 0) g_part[blockIdx.x] = make_float2(sr_s[0], sf_s[0]);
}

__global__ void norm_final(float* __restrict__ out) {
    __shared__ float sr_s[256], sf_s[256];
    float2 v = g_part[threadIdx.x];
    sr_s[threadIdx.x] = v.x;
    sf_s[threadIdx.x] = v.y;
    __syncthreads();
    for (int o = 128; o > 0; o >>= 1) {
        if (threadIdx.x < o) {
            sr_s[threadIdx.x] += sr_s[threadIdx.x + o];
            sf_s[threadIdx.x] += sf_s[threadIdx.x + o];
        }
        __syncthreads();
    }
    if (threadIdx.x == 0) out[0] = sqrtf(sr_s[0] / sf_s[0]);
}

// ---------------- launch ------------------------------------------------------
extern "C" void kernel_launch(void* const* d_in, const int* in_sizes, int n_in,
                              void* d_out, int out_size) {
    (void)in_sizes; (void)n_in; (void)out_size;
    const float* f   = (const float*)d_in[0];
    const float* kA  = (const float*)d_in[1];
    const float* w1r = (const float*)d_in[2];
    const float* w1i = (const float*)d_in[3];
    const float* w2r = (const float*)d_in[4];
    const float* w2i = (const float*)d_in[5];
    const float* w3r = (const float*)d_in[6];
    const float* w3i = (const float*)d_in[7];
    const float* thr = (const float*)d_in[8];
    const float* thi = (const float*)d_in[9];
    const int*   ep  = (const int*)d_in[10];
    float* out = (float*)d_out;

    void *pFA = nullptr, *pFB = nullptr;
    cudaGetSymbolAddress(&pFA, g_FA);
    cudaGetSymbolAddress(&pFB, g_FB);

    const int CSM = 256 * 32 * 8 + 128 * 8;            // 66560 B
    const int FSM = (1444 + 5184 + 216) * 8;           // 54752 B
    cudaFuncSetAttribute(fft_col_inv, cudaFuncAttributeMaxDynamicSharedMemorySize, CSM);
    cudaFuncSetAttribute(fft_col_fwd_accum, cudaFuncAttributeMaxDynamicSharedMemorySize, CSM);
    cudaFuncSetAttribute(fused_stack<false>, cudaFuncAttributeMaxDynamicSharedMemorySize, FSM);
    cudaFuncSetAttribute(fused_stack<true>,  cudaFuncAttributeMaxDynamicSharedMemorySize, FSM);

    zero_x_kernel<<<(NB * NN + 255) / 256, 256>>>();

    dim3 jg(4, 4, NB);
    for (int it = 0; it < 3; ++it) {
        jacobi_tile<<<jg, 256>>>(f, kA, ep, it, 0);
        jacobi_tile<<<jg, 256>>>(f, kA, ep, it, 0);
        jacobi_tile<<<jg, 256>>>(f, kA, ep, it, 0);
        jacobi_tile<<<jg, 256>>>(f, kA, ep, it, 1);
        fft_row_expand<<<dim3(32, NB), dim3(128, 4)>>>(ep, it);
        fft_col_inv<<<dim3(8, NB), dim3(32, 32), CSM>>>(ep, it);
        fused_stack<false><<<dim3(8, 8, NB), 512, FSM>>>(
            (const float2*)pFB, (float2*)pFA,
            w1r, w1i, w2r, w2i, w3r, w3i, thr, thi, ep, it);
        fused_stack<true><<<dim3(8, 8, NB), 512, FSM>>>(
            (const float2*)pFA, (float2*)pFB,
            w1r, w1i, w2r, w2i, w3r, w3i, nullptr, nullptr, ep, it);
        fft_row_fwd<<<dim3(64, NB), dim3(128, 4)>>>(ep, it);
        fft_col_fwd_accum<<<dim3(4, NB), dim3(32, 32), CSM>>>(ep, it);
    }

    norm_partial<<<256, 256>>>(f, kA);
    norm_final<<<1, 256>>>(out);
}

// round 6
// speedup vs baseline: 1.3082x; 1.0103x over previous
#include <cuda_runtime.h>
#include <math.h>

#define NB   16
#define NI   127
#define NN   16129      // 127*127
#define IMG  65536      // 256*256
#define TS   32
#define HL2  11
#define LT2  54         // TS + 2*HL2
#define LTN  2916       // LT2*LT2

// ---------------- scratch (static device globals) ----------------------------
static __device__ float  g_x[NB * NN];
static __device__ float  g_r[NB * NN];
static __device__ float2 g_FA[NB * IMG];
static __device__ float2 g_FB[NB * IMG];
static __device__ float2 g_part[256];

// ---------------- helpers ----------------------------------------------------
__device__ __forceinline__ int get_K(const int* ep) {
    int ei = *ep;
    int e;
    if (ei > 0 && ei <= 1000000) {
        e = ei;
    } else {
        float ff = __int_as_float(ei);
        e = (ff >= 1.0f && ff <= 1000000.0f) ? (int)ff : 120;
    }
    int K = (e - 1) / 40 + 1;
    if (K > 10) K = 10;
    if (K < 1)  K = 1;
    return K;
}

__device__ __forceinline__ int rev8(int x) { return (int)(__brev((unsigned)x) >> 24); }

__device__ __forceinline__ void build_tw(float2* tw, int tid, float sign) {
    if (tid < 128) {
        float s, c;
        __sincosf(sign * 6.283185307179586f * (float)tid * (1.0f / 256.0f), &s, &c);
        tw[tid] = make_float2(c, s);
    }
}

// In-place 256-pt DIT FFT (bit-reversed input); 128 threads per row, 1 bfly each.
__device__ __forceinline__ void fft256_ip(float2* s, const float2* tw, int t) {
#pragma unroll
    for (int st = 1; st <= 8; ++st) {
        int mh  = 1 << (st - 1);
        int idx = ((t >> (st - 1)) << st) | (t & (mh - 1));
        int twi = (t & (mh - 1)) << (8 - st);
        float2 w = tw[twi];
        float2 u = s[idx];
        float2 v = s[idx + mh];
        float vr = v.x * w.x - v.y * w.y;
        float vi = v.x * w.y + v.y * w.x;
        s[idx]      = make_float2(u.x + vr, u.y + vi);
        s[idx + mh] = make_float2(u.x - vr, u.y - vi);
        __syncthreads();
    }
}

// ---------------- kernels ----------------------------------------------------
__global__ void zero_x_kernel() {
    int i = blockIdx.x * blockDim.x + threadIdx.x;
    if (i < NB * NN) g_x[i] = 0.0f;
}

// Sweep-chunked Jacobi: 10 sweeps per launch on 54x54 tiles (halo 11),
// 512 threads, per-thread indices hoisted out of the sweep loop.
// final!=0: also emit r = f - A x on the 32x32 interior.
__global__ void __launch_bounds__(512)
jacobi_tile(const float* __restrict__ f, const float* __restrict__ kA,
            const int* __restrict__ ep, int iter, int final_) {
    if (iter >= get_K(ep)) return;
    __shared__ float xs0[LTN], xs1[LTN], fs[LTN];
    int b  = blockIdx.z;
    int ox = blockIdx.x * TS - HL2;
    int oy = blockIdx.y * TS - HL2;
    int tid = threadIdx.x;
    const float* ka = kA + b * 9;
    float k0 = ka[0], k1 = ka[1], k2 = ka[2], k3 = ka[3], k4 = ka[4];
    float k5 = ka[5], k6 = ka[6], k7 = ka[7], k8 = ka[8];
    float tau = 0.5f / k4;

    // load tile + hoist per-element indices
    int  iyk[6], ixk[6];
    bool okk[6], domk[6];
#pragma unroll
    for (int k = 0; k < 6; ++k) {
        int p = tid + k * 512;
        bool ok = p < LTN;
        int iy = 0, ix = 0;
        if (ok) { iy = p / LT2; ix = p - iy * LT2; }
        int gy = oy + iy, gx = ox + ix;
        bool dom = ok && ((unsigned)gy < 127u) && ((unsigned)gx < 127u);
        if (ok) {
            xs0[p] = dom ? g_x[b * NN + gy * 127 + gx] : 0.0f;
            fs[p]  = dom ? f[b * NN + gy * 127 + gx] : 0.0f;
        }
        iyk[k] = iy; ixk[k] = ix; okk[k] = ok; domk[k] = dom;
    }
    __syncthreads();

    float* cur = xs0;
    float* nxt = xs1;
#pragma unroll
    for (int s = 0; s < 10; ++s) {
        int a = s + 1;
#pragma unroll
        for (int k = 0; k < 6; ++k) {
            if (okk[k]) {
                int p = tid + k * 512;
                float nv = cur[p];
                int iy = iyk[k], ix = ixk[k];
                if (domk[k] && iy >= a && iy < LT2 - a && ix >= a && ix < LT2 - a) {
                    float ax = k0 * cur[p - LT2 - 1] + k1 * cur[p - LT2] + k2 * cur[p - LT2 + 1]
                             + k3 * cur[p - 1]       + k4 * cur[p]       + k5 * cur[p + 1]
                             + k6 * cur[p + LT2 - 1] + k7 * cur[p + LT2] + k8 * cur[p + LT2 + 1];
                    nv = cur[p] + tau * (fs[p] - ax);
                }
                nxt[p] = nv;
            }
        }
        __syncthreads();
        float* tsw = cur; cur = nxt; nxt = tsw;
    }

#pragma unroll
    for (int k = 0; k < 2; ++k) {
        int p2 = tid + k * 512;
        int py = p2 >> 5, px = p2 & 31;
        int iy = HL2 + py, ix = HL2 + px;
        int gy = oy + iy, gx = ox + ix;
        if (((unsigned)gy < 127u) && ((unsigned)gx < 127u)) {
            int i = iy * LT2 + ix;
            g_x[b * NN + gy * 127 + gx] = cur[i];
            if (final_) {
                float ax = k0 * cur[i - LT2 - 1] + k1 * cur[i - LT2] + k2 * cur[i - LT2 + 1]
                         + k3 * cur[i - 1]       + k4 * cur[i]       + k5 * cur[i + 1]
                         + k6 * cur[i + LT2 - 1] + k7 * cur[i + LT2] + k8 * cur[i + LT2 + 1];
                g_r[b * NN + gy * 127 + gx] = fs[i] - ax;
            }
        }
    }
}

// ifft2 pass 1 (odd symmetry): rows 1..127 FFT'd, row 256-y = -row y. 4 rows/block.
__global__ void __launch_bounds__(512)
fft_row_expand(const int* __restrict__ ep, int iter) {
    if (iter >= get_K(ep)) return;
    __shared__ float2 s[4][256];
    __shared__ float2 tw[128];
    int b = blockIdx.y, t = threadIdx.x, ty = threadIdx.y;
    int y = blockIdx.x * 4 + ty + 1;            // 1..128 (128 invalid)
    bool ok = (y <= 127);
    build_tw(tw, ty * 128 + t, 1.0f);
    const float* rrow = g_r + (b * NN + (ok ? (y - 1) : 0) * 127);
#pragma unroll
    for (int k = 0; k < 2; ++k) {
        int p = t + k * 128;
        float v = 0.0f;
        if (ok) {
            if (p >= 1 && p <= 127)  v =  rrow[p - 1];
            else if (p >= 129)       v = -rrow[255 - p];
        }
        s[ty][rev8(p)] = make_float2(v, 0.0f);
    }
    __syncthreads();
    fft256_ip(s[ty], tw, t);
    if (ok) {
        float2* base = g_FA + (size_t)b * IMG;
        float2 v0 = s[ty][t], v1 = s[ty][t + 128];
        base[y * 256 + t]               = v0;
        base[y * 256 + t + 128]         = v1;
        base[(256 - y) * 256 + t]       = make_float2(-v0.x, -v0.y);
        base[(256 - y) * 256 + t + 128] = make_float2(-v1.x, -v1.y);
        if (y == 1) {
            base[t]                   = make_float2(0.f, 0.f);
            base[t + 128]             = make_float2(0.f, 0.f);
            base[128 * 256 + t]       = make_float2(0.f, 0.f);
            base[128 * 256 + t + 128] = make_float2(0.f, 0.f);
        }
    }
}

// ifft2 pass 2: 16-col tiles, block (16,64)=1024 thr, scale, fftshift write.
__global__ void __launch_bounds__(1024)
fft_col_inv(const int* __restrict__ ep, int iter) {
    if (iter >= get_K(ep)) return;
    __shared__ float2 s[256 * 16];
    __shared__ float2 tw[128];
    int b  = blockIdx.y;
    int tx = threadIdx.x, ty = threadIdx.y;     // 16 x 64
    int tid = ty * 16 + tx;
    int x = blockIdx.x * 16 + tx;
    build_tw(tw, tid, 1.0f);
    for (int r = ty; r < 256; r += 64)
        s[rev8(r) * 16 + tx] = g_FA[(b * 256 + r) * 256 + x];
    __syncthreads();
#pragma unroll
    for (int st = 1; st <= 8; ++st) {
        int mh = 1 << (st - 1);
#pragma unroll
        for (int k = 0; k < 2; ++k) {
            int i   = ty + 64 * k;
            int idx = ((i >> (st - 1)) << st) | (i & (mh - 1));
            int twi = (i & (mh - 1)) << (8 - st);
            float2 w = tw[twi];
            float2 u = s[idx * 16 + tx];
            float2 v = s[(idx + mh) * 16 + tx];
            float vr = v.x * w.x - v.y * w.y;
            float vi = v.x * w.y + v.y * w.x;
            s[idx * 16 + tx]        = make_float2(u.x + vr, u.y + vi);
            s[(idx + mh) * 16 + tx] = make_float2(u.x - vr, u.y - vi);
        }
        __syncthreads();
    }
    const float sc = 1.0f / 65536.0f;
    int xo = x ^ 128;
    for (int r = ty; r < 256; r += 64) {
        float2 v = s[r * 16 + tx];
        g_FB[(b * 256 + (r ^ 128)) * 256 + xo] = make_float2(v.x * sc, v.y * sc);
    }
}

// Fused 3-conv stack, 512 threads, smem 55KB (T2 aliases T1).
template <bool ADJ>
__global__ void __launch_bounds__(512, 2)
fused_stack(const float2* __restrict__ in, float2* __restrict__ out,
            const float* __restrict__ w1r, const float* __restrict__ w1i,
            const float* __restrict__ w2r, const float* __restrict__ w2i,
            const float* __restrict__ w3r, const float* __restrict__ w3i,
            const float* __restrict__ thr, const float* __restrict__ thi,
            const int* __restrict__ ep, int iter) {
    if (iter >= get_K(ep)) return;
    extern __shared__ float2 sm[];
    float2* IN = sm;                  // 38*38 = 1444
    float2* T1 = sm + 1444;           // 4*36*36 = 5184 (later reused as T2 4*1156)
    float2* Wa = sm + 1444 + 5184;    // [9][4]
    float2* Wb = Wa + 36;             // [4][9][4]
    float2* Wc = Wa + 180;            // [4][9]

    int b   = blockIdx.z;
    int ox  = blockIdx.x * 32;
    int oy  = blockIdx.y * 32;
    int tid = threadIdx.x;

    if (tid < 216) {
        if (tid < 36) {
            int tap = tid >> 2, co = tid & 3;
            if (!ADJ) {
                int j = (b * 4 + co) * 9 + tap;
                Wa[tid] = make_float2(w1r[j], w1i[j]);
            } else {
                int tt = (tap % 3) * 3 + tap / 3;
                int j = (b * 4 + co) * 9 + tt;
                Wa[tid] = make_float2(w3r[j], -w3i[j]);
            }
        } else if (tid < 180) {
            int u = tid - 36;
            int ci = u / 36, tap = (u % 36) >> 2, co = u & 3;
            if (!ADJ) {
                int j = ((b * 4 + co) * 4 + ci) * 9 + tap;
                Wb[u] = make_float2(w2r[j], w2i[j]);
            } else {
                int tt = (tap % 3) * 3 + tap / 3;
                int j = ((b * 4 + ci) * 4 + co) * 9 + tt;
                Wb[u] = make_float2(w2r[j], -w2i[j]);
            }
        } else {
            int u = tid - 180;
            int ci = u / 9, tap = u % 9;
            if (!ADJ) {
                int j = (b * 4 + ci) * 9 + tap;
                Wc[u] = make_float2(w3r[j], w3i[j]);
            } else {
                int tt = (tap % 3) * 3 + tap / 3;
                int j = (b * 4 + ci) * 9 + tt;
                Wc[u] = make_float2(w1r[j], -w1i[j]);
            }
        }
    }

    const float2* inb = in + (size_t)b * IMG;
    for (int i = tid; i < 38 * 38; i += 512) {
        int iy = i / 38, ix = i % 38;
        int gy = oy - 3 + iy, gx = ox - 3 + ix;
        float2 v = make_float2(0.0f, 0.0f);
        if ((unsigned)gy < 256u && (unsigned)gx < 256u) v = inb[gy * 256 + gx];
        IN[i] = v;
    }
    __syncthreads();

    // stage 1: 1 -> 4 over 36x36
    for (int p = tid; p < 1296; p += 512) {
        int py = p / 36, px = p % 36;
        int gy = oy - 2 + py, gx = ox - 2 + px;
        float2 a0 = make_float2(0.f, 0.f), a1 = a0, a2 = a0, a3 = a0;
        if ((unsigned)gy < 256u && (unsigned)gx < 256u) {
            int base = py * 38 + px;
#pragma unroll
            for (int tap = 0; tap < 9; ++tap) {
                float2 v = IN[base + (tap / 3) * 38 + tap % 3];
                float2 w;
                w = Wa[tap * 4 + 0]; a0.x += v.x*w.x - v.y*w.y; a0.y += v.x*w.y + v.y*w.x;
                w = Wa[tap * 4 + 1]; a1.x += v.x*w.x - v.y*w.y; a1.y += v.x*w.y + v.y*w.x;
                w = Wa[tap * 4 + 2]; a2.x += v.x*w.x - v.y*w.y; a2.y += v.x*w.y + v.y*w.x;
                w = Wa[tap * 4 + 3]; a3.x += v.x*w.x - v.y*w.y; a3.y += v.x*w.y + v.y*w.x;
            }
        }
        T1[0 * 1296 + p] = a0;
        T1[1 * 1296 + p] = a1;
        T1[2 * 1296 + p] = a2;
        T1[3 * 1296 + p] = a3;
    }
    __syncthreads();

    // stage 2: 4 -> 4 over 34x34; clamped indices (branch-free inner loop)
    {
        float2 acc[3][4];
        int bidx[3];
        bool val[3];
#pragma unroll
        for (int k = 0; k < 3; ++k) {
            int p = tid + k * 512;
            val[k] = p < 1156;
            int pc = val[k] ? p : 1155;
            int py = pc / 34, px = pc - py * 34;
            bidx[k] = py * 36 + px;
#pragma unroll
            for (int c = 0; c < 4; ++c) acc[k][c] = make_float2(0.f, 0.f);
        }
#pragma unroll
        for (int ci = 0; ci < 4; ++ci) {
            const float2* Tci = T1 + ci * 1296;
#pragma unroll
            for (int tap = 0; tap < 9; ++tap) {
                float2 w0 = Wb[(ci * 9 + tap) * 4 + 0];
                float2 w1 = Wb[(ci * 9 + tap) * 4 + 1];
                float2 w2 = Wb[(ci * 9 + tap) * 4 + 2];
                float2 w3 = Wb[(ci * 9 + tap) * 4 + 3];
                int off = (tap / 3) * 36 + tap % 3;
#pragma unroll
                for (int k = 0; k < 3; ++k) {
                    float2 v = Tci[bidx[k] + off];
                    acc[k][0].x += v.x*w0.x - v.y*w0.y; acc[k][0].y += v.x*w0.y + v.y*w0.x;
                    acc[k][1].x += v.x*w1.x - v.y*w1.y; acc[k][1].y += v.x*w1.y + v.y*w1.x;
                    acc[k][2].x += v.x*w2.x - v.y*w2.y; acc[k][2].y += v.x*w2.y + v.y*w2.x;
                    acc[k][3].x += v.x*w3.x - v.y*w3.y; acc[k][3].y += v.x*w3.y + v.y*w3.x;
                }
            }
        }
        __syncthreads();   // all T1 reads complete; safe to overwrite with T2
#pragma unroll
        for (int k = 0; k < 3; ++k) {
            if (val[k]) {
                int p = tid + k * 512;
                int py = p / 34, px = p - py * 34;
                int gy = oy - 1 + py, gx = ox - 1 + px;
                bool inb2 = ((unsigned)gy < 256u) && ((unsigned)gx < 256u);
#pragma unroll
                for (int c = 0; c < 4; ++c)
                    T1[c * 1156 + p] = inb2 ? acc[k][c] : make_float2(0.f, 0.f);
            }
        }
    }
    __syncthreads();

    // stage 3: 4 -> 1 over 32x32
    {
        float2 acc[2];
        int bidx[2];
#pragma unroll
        for (int k = 0; k < 2; ++k) {
            int p = tid + k * 512;
            int py = p >> 5, px = p & 31;
            bidx[k] = py * 34 + px;
            acc[k] = make_float2(0.f, 0.f);
        }
#pragma unroll
        for (int ci = 0; ci < 4; ++ci) {
            const float2* Tci = T1 + ci * 1156;
#pragma unroll
            for (int tap = 0; tap < 9; ++tap) {
                float2 w = Wc[ci * 9 + tap];
                int off = (tap / 3) * 34 + tap % 3;
#pragma unroll
                for (int k = 0; k < 2; ++k) {
                    float2 v = Tci[bidx[k] + off];
                    acc[k].x += v.x*w.x - v.y*w.y;
                    acc[k].y += v.x*w.y + v.y*w.x;
                }
            }
        }
        float2* ob = out + (size_t)b * IMG;
#pragma unroll
        for (int k = 0; k < 2; ++k) {
            int p = tid + k * 512;
            int py = p >> 5, px = p & 31;
            int gidx = (oy + py) * 256 + (ox + px);
            float2 v = acc[k];
            if (!ADJ) {
                float tr = thr[b * IMG + gidx], ti = thi[b * IMG + gidx];
                v = make_float2(v.x * tr - v.y * ti, v.x * ti + v.y * tr);
            }
            ob[gidx] = v;
        }
    }
}

// fft2 pass 1: ifftshift on read, forward FFT along x. 4 rows/block.
__global__ void __launch_bounds__(512)
fft_row_fwd(const int* __restrict__ ep, int iter) {
    if (iter >= get_K(ep)) return;
    __shared__ float2 s[4][256];
    __shared__ float2 tw[128];
    int b = blockIdx.y, t = threadIdx.x, ty = threadIdx.y;
    int y = blockIdx.x * 4 + ty;
    build_tw(tw, ty * 128 + t, -1.0f);
    const float2* irow = g_FB + (b * 256 + (y ^ 128)) * 256;
#pragma unroll
    for (int k = 0; k < 2; ++k) {
        int p = t + k * 128;
        s[ty][rev8(p)] = irow[p ^ 128];
    }
    __syncthreads();
    fft256_ip(s[ty], tw, t);
    float2* orow = g_FA + (b * 256 + y) * 256;
    orow[t]       = s[ty][t];
    orow[t + 128] = s[ty][t + 128];
}

// fft2 pass 2: 16-col tiles, block (16,64), crop 127x127, accumulate into x.
__global__ void __launch_bounds__(1024)
fft_col_fwd_accum(const int* __restrict__ ep, int iter) {
    if (iter >= get_K(ep)) return;
    __shared__ float2 s[256 * 16];
    __shared__ float2 tw[128];
    int b  = blockIdx.y;
    int tx = threadIdx.x, ty = threadIdx.y;
    int tid = ty * 16 + tx;
    int x = blockIdx.x * 16 + tx;
    build_tw(tw, tid, -1.0f);
    for (int r = ty; r < 256; r += 64)
        s[rev8(r) * 16 + tx] = g_FA[(b * 256 + r) * 256 + x];
    __syncthreads();
#pragma unroll
    for (int st = 1; st <= 8; ++st) {
        int mh = 1 << (st - 1);
#pragma unroll
        for (int k = 0; k < 2; ++k) {
            int i   = ty + 64 * k;
            int idx = ((i >> (st - 1)) << st) | (i & (mh - 1));
            int twi = (i & (mh - 1)) << (8 - st);
            float2 w = tw[twi];
            float2 u = s[idx * 16 + tx];
            float2 v = s[(idx + mh) * 16 + tx];
            float vr = v.x * w.x - v.y * w.y;
            float vi = v.x * w.y + v.y * w.x;
            s[idx * 16 + tx]        = make_float2(u.x + vr, u.y + vi);
            s[(idx + mh) * 16 + tx] = make_float2(u.x - vr, u.y - vi);
        }
        __syncthreads();
    }
    if (x < 127) {
        for (int r = ty; r < 127; r += 64)
            g_x[b * NN + r * 127 + x] += s[r * 16 + tx].x;
    }
}

// Final residual norm.
__global__ void norm_partial(const float* __restrict__ f, const float* __restrict__ kA) {
    __shared__ float sr_s[256], sf_s[256];
    float sr = 0.0f, sf = 0.0f;
    for (int idx = blockIdx.x * 256 + threadIdx.x; idx < NB * NN; idx += 256 * 256) {
        int b = idx / NN;
        int p = idx - b * NN;
        int y = p / 127, x = p - y * 127;
        const float* ka = kA + b * 9;
        const float* xb = g_x + b * NN;
        float s = 0.0f;
        if (y > 0) {
            if (x > 0)   s += ka[0] * xb[p - 128];
            s += ka[1] * xb[p - 127];
            if (x < 126) s += ka[2] * xb[p - 126];
        }
        if (x > 0)   s += ka[3] * xb[p - 1];
        s += ka[4] * xb[p];
        if (x < 126) s += ka[5] * xb[p + 1];
        if (y < 126) {
            if (x > 0)   s += ka[6] * xb[p + 126];
            s += ka[7] * xb[p + 127];
            if (x < 126) s += ka[8] * xb[p + 128];
        }
        float fv = f[idx];
        float rv = fv - s;
        sr += rv * rv;
        sf += fv * fv;
    }
    sr_s[threadIdx.x] = sr;
    sf_s[threadIdx.x] = sf;
    __syncthreads();
    for (int o = 128; o > 0; o >>= 1) {
        if (threadIdx.x < o) {
            sr_s[threadIdx.x] += sr_s[threadIdx.x + o];
            sf_s[threadIdx.x] += sf_s[threadIdx.x + o];
        }
        __syncthreads();
    }
    if (threadIdx.x == 0) g_part[blockIdx.x] = make_float2(sr_s[0], sf_s[0]);
}

__global__ void norm_final(float* __restrict__ out) {
    __shared__ float sr_s[256], sf_s[256];
    float2 v = g_part[threadIdx.x];
    sr_s[threadIdx.x] = v.x;
    sf_s[threadIdx.x] = v.y;
    __syncthreads();
    for (int o = 128; o > 0; o >>= 1) {
        if (threadIdx.x < o) {
            sr_s[threadIdx.x] += sr_s[threadIdx.x + o];
            sf_s[threadIdx.x] += sf_s[threadIdx.x + o];
        }
        __syncthreads();
    }
    if (threadIdx.x == 0) out[0] = sqrtf(sr_s[0] / sf_s[0]);
}

// ---------------- launch ------------------------------------------------------
extern "C" void kernel_launch(void* const* d_in, const int* in_sizes, int n_in,
                              void* d_out, int out_size) {
    (void)in_sizes; (void)n_in; (void)out_size;
    const float* f   = (const float*)d_in[0];
    const float* kA  = (const float*)d_in[1];
    const float* w1r = (const float*)d_in[2];
    const float* w1i = (const float*)d_in[3];
    const float* w2r = (const float*)d_in[4];
    const float* w2i = (const float*)d_in[5];
    const float* w3r = (const float*)d_in[6];
    const float* w3i = (const float*)d_in[7];
    const float* thr = (const float*)d_in[8];
    const float* thi = (const float*)d_in[9];
    const int*   ep  = (const int*)d_in[10];
    float* out = (float*)d_out;

    void *pFA = nullptr, *pFB = nullptr;
    cudaGetSymbolAddress(&pFA, g_FA);
    cudaGetSymbolAddress(&pFB, g_FB);

    const int FSM = (1444 + 5184 + 216) * 8;           // 54752 B
    cudaFuncSetAttribute(fused_stack<false>, cudaFuncAttributeMaxDynamicSharedMemorySize, FSM);
    cudaFuncSetAttribute(fused_stack<true>,  cudaFuncAttributeMaxDynamicSharedMemorySize, FSM);

    zero_x_kernel<<<(NB * NN + 255) / 256, 256>>>();

    dim3 jg(4, 4, NB);
    for (int it = 0; it < 3; ++it) {
        jacobi_tile<<<jg, 512>>>(f, kA, ep, it, 0);
        jacobi_tile<<<jg, 512>>>(f, kA, ep, it, 1);
        fft_row_expand<<<dim3(32, NB), dim3(128, 4)>>>(ep, it);
        fft_col_inv<<<dim3(16, NB), dim3(16, 64)>>>(ep, it);
        fused_stack<false><<<dim3(8, 8, NB), 512, FSM>>>(
            (const float2*)pFB, (float2*)pFA,
            w1r, w1i, w2r, w2i, w3r, w3i, thr, thi, ep, it);
        fused_stack<true><<<dim3(8, 8, NB), 512, FSM>>>(
            (const float2*)pFA, (float2*)pFB,
            w1r, w1i, w2r, w2i, w3r, w3i, nullptr, nullptr, ep, it);
        fft_row_fwd<<<dim3(64, NB), dim3(128, 4)>>>(ep, it);
        fft_col_fwd_accum<<<dim3(8, NB), dim3(16, 64)>>>(ep, it);
    }

    norm_partial<<<256, 256>>>(f, kA);
    norm_final<<<1, 256>>>(out);
}

// round 7
// speedup vs baseline: 1.5432x; 1.1797x over previous
#include <cuda_runtime.h>
#include <math.h>

#define NB   16
#define NI   127
#define NN   16129      // 127*127
#define IMG  65536      // 256*256
#define TS   32
#define HL2  11
#define LT2  54         // TS + 2*HL2
#define LTN  2916       // LT2*LT2

typedef unsigned long long u64;

// ---------------- scratch (static device globals) ----------------------------
static __device__ float  g_x[NB * NN];
static __device__ float  g_r[NB * NN];
static __device__ float2 g_FA[NB * IMG];
static __device__ float2 g_FB[NB * IMG];   // first half also used as float buffer
static __device__ float2 g_part[1024];

// ---------------- packed f32x2 helpers ---------------------------------------
__device__ __forceinline__ u64 pk2(float lo, float hi) {
    u64 r; asm("mov.b64 %0, {%1, %2};" : "=l"(r) : "f"(lo), "f"(hi)); return r;
}
__device__ __forceinline__ float2 upk(u64 v) {
    float2 r; asm("mov.b64 {%0, %1}, %2;" : "=f"(r.x), "=f"(r.y) : "l"(v)); return r;
}
__device__ __forceinline__ void cfma(u64& acc, u64 a, u64 b) {
    asm("fma.rn.f32x2 %0, %1, %2, %0;" : "+l"(acc) : "l"(a), "l"(b));
}

// ---------------- misc helpers ------------------------------------------------
__device__ __forceinline__ int get_K(const int* ep) {
    int ei = *ep;
    int e;
    if (ei > 0 && ei <= 1000000) {
        e = ei;
    } else {
        float ff = __int_as_float(ei);
        e = (ff >= 1.0f && ff <= 1000000.0f) ? (int)ff : 120;
    }
    int K = (e - 1) / 40 + 1;
    if (K > 10) K = 10;
    if (K < 1)  K = 1;
    return K;
}

__device__ __forceinline__ int rev8(int x) { return (int)(__brev((unsigned)x) >> 24); }

__device__ __forceinline__ void build_tw(float2* tw, int tid, float sign) {
    if (tid < 128) {
        float s, c;
        __sincosf(sign * 6.283185307179586f * (float)tid * (1.0f / 256.0f), &s, &c);
        tw[tid] = make_float2(c, s);
    }
}

// In-place 256-pt DIT FFT (bit-reversed input); 128 threads per row, 1 bfly each.
__device__ __forceinline__ void fft256_ip(float2* s, const float2* tw, int t) {
#pragma unroll
    for (int st = 1; st <= 8; ++st) {
        int mh  = 1 << (st - 1);
        int idx = ((t >> (st - 1)) << st) | (t & (mh - 1));
        int twi = (t & (mh - 1)) << (8 - st);
        float2 w = tw[twi];
        float2 u = s[idx];
        float2 v = s[idx + mh];
        float vr = v.x * w.x - v.y * w.y;
        float vi = v.x * w.y + v.y * w.x;
        s[idx]      = make_float2(u.x + vr, u.y + vi);
        s[idx + mh] = make_float2(u.x - vr, u.y - vi);
        __syncthreads();
    }
}

// ---------------- kernels ----------------------------------------------------
// Sweep-chunked Jacobi: 10 sweeps/launch on 54x54 tiles (halo 11), 512 threads.
// zero!=0: treat incoming x as 0 (skip load). final!=0: emit r = f - A x.
__global__ void __launch_bounds__(512)
jacobi_tile(const float* __restrict__ f, const float* __restrict__ kA,
            const int* __restrict__ ep, int iter, int final_, int zero) {
    if (iter >= get_K(ep)) return;
    __shared__ float xs0[LTN], xs1[LTN], fs[LTN];
    int b  = blockIdx.z;
    int ox = blockIdx.x * TS - HL2;
    int oy = blockIdx.y * TS - HL2;
    int tid = threadIdx.x;
    const float* ka = kA + b * 9;
    float k0 = ka[0], k1 = ka[1], k2 = ka[2], k3 = ka[3], k4 = ka[4];
    float k5 = ka[5], k6 = ka[6], k7 = ka[7], k8 = ka[8];
    float tau = 0.5f / k4;

    int  iyk[6], ixk[6];
    bool okk[6], domk[6];
#pragma unroll
    for (int k = 0; k < 6; ++k) {
        int p = tid + k * 512;
        bool ok = p < LTN;
        int iy = 0, ix = 0;
        if (ok) { iy = p / LT2; ix = p - iy * LT2; }
        int gy = oy + iy, gx = ox + ix;
        bool dom = ok && ((unsigned)gy < 127u) && ((unsigned)gx < 127u);
        if (ok) {
            xs0[p] = (dom && !zero) ? g_x[b * NN + gy * 127 + gx] : 0.0f;
            fs[p]  = dom ? f[b * NN + gy * 127 + gx] : 0.0f;
        }
        iyk[k] = iy; ixk[k] = ix; okk[k] = ok; domk[k] = dom;
    }
    __syncthreads();

    float* cur = xs0;
    float* nxt = xs1;
#pragma unroll
    for (int s = 0; s < 10; ++s) {
        int a = s + 1;
#pragma unroll
        for (int k = 0; k < 6; ++k) {
            if (okk[k]) {
                int p = tid + k * 512;
                float nv = cur[p];
                int iy = iyk[k], ix = ixk[k];
                if (domk[k] && iy >= a && iy < LT2 - a && ix >= a && ix < LT2 - a) {
                    float ax = k0 * cur[p - LT2 - 1] + k1 * cur[p - LT2] + k2 * cur[p - LT2 + 1]
                             + k3 * cur[p - 1]       + k4 * cur[p]       + k5 * cur[p + 1]
                             + k6 * cur[p + LT2 - 1] + k7 * cur[p + LT2] + k8 * cur[p + LT2 + 1];
                    nv = cur[p] + tau * (fs[p] - ax);
                }
                nxt[p] = nv;
            }
        }
        __syncthreads();
        float* tsw = cur; cur = nxt; nxt = tsw;
    }

#pragma unroll
    for (int k = 0; k < 2; ++k) {
        int p2 = tid + k * 512;
        int py = p2 >> 5, px = p2 & 31;
        int iy = HL2 + py, ix = HL2 + px;
        int gy = oy + iy, gx = ox + ix;
        if (((unsigned)gy < 127u) && ((unsigned)gx < 127u)) {
            int i = iy * LT2 + ix;
            g_x[b * NN + gy * 127 + gx] = cur[i];
            if (final_) {
                float ax = k0 * cur[i - LT2 - 1] + k1 * cur[i - LT2] + k2 * cur[i - LT2 + 1]
                         + k3 * cur[i - 1]       + k4 * cur[i]       + k5 * cur[i + 1]
                         + k6 * cur[i + LT2 - 1] + k7 * cur[i + LT2] + k8 * cur[i + LT2 + 1];
                g_r[b * NN + gy * 127 + gx] = fs[i] - ax;
            }
        }
    }
}

// ifft2 pass 1 (odd symmetry): FFT rows 1..127; store only k=0..127.
// Row 256-y = -row y; rows 0,128 zero.
__global__ void __launch_bounds__(512)
fft_row_expand(const int* __restrict__ ep, int iter) {
    if (iter >= get_K(ep)) return;
    __shared__ float2 s[4][256];
    __shared__ float2 tw[128];
    int b = blockIdx.y, t = threadIdx.x, ty = threadIdx.y;
    int y = blockIdx.x * 4 + ty + 1;            // 1..128 (128 invalid)
    bool ok = (y <= 127);
    build_tw(tw, ty * 128 + t, 1.0f);
    const float* rrow = g_r + (b * NN + (ok ? (y - 1) : 0) * 127);
#pragma unroll
    for (int k = 0; k < 2; ++k) {
        int p = t + k * 128;
        float v = 0.0f;
        if (ok) {
            if (p >= 1 && p <= 127)  v =  rrow[p - 1];
            else if (p >= 129)       v = -rrow[255 - p];
        }
        s[ty][rev8(p)] = make_float2(v, 0.0f);
    }
    __syncthreads();
    fft256_ip(s[ty], tw, t);
    if (ok) {
        float2* base = g_FA + (size_t)b * IMG;
        float2 v0 = s[ty][t];                   // k = t (0..127)
        base[y * 256 + t]         = v0;
        base[(256 - y) * 256 + t] = make_float2(-v0.x, -v0.y);
        if (y == 1) {
            base[t]             = make_float2(0.f, 0.f);
            base[128 * 256 + t] = make_float2(0.f, 0.f);
        }
    }
}

// ifft2 pass 2: columns 0..127 only; output purely REAL (odd-odd input).
// Write real part scaled, with fftshift; mirror columns by negation.
__global__ void __launch_bounds__(1024)
fft_col_inv(const int* __restrict__ ep, int iter) {
    if (iter >= get_K(ep)) return;
    __shared__ float2 s[256 * 16];
    __shared__ float2 tw[128];
    int b  = blockIdx.y;
    int tx = threadIdx.x, ty = threadIdx.y;     // 16 x 64
    int tid = ty * 16 + tx;
    int x = blockIdx.x * 16 + tx;               // 0..127
    build_tw(tw, tid, 1.0f);
    for (int r = ty; r < 256; r += 64)
        s[rev8(r) * 16 + tx] = g_FA[(b * 256 + r) * 256 + x];
    __syncthreads();
#pragma unroll
    for (int st = 1; st <= 8; ++st) {
        int mh = 1 << (st - 1);
#pragma unroll
        for (int k = 0; k < 2; ++k) {
            int i   = ty + 64 * k;
            int idx = ((i >> (st - 1)) << st) | (i & (mh - 1));
            int twi = (i & (mh - 1)) << (8 - st);
            float2 w = tw[twi];
            float2 u = s[idx * 16 + tx];
            float2 v = s[(idx + mh) * 16 + tx];
            float vr = v.x * w.x - v.y * w.y;
            float vi = v.x * w.y + v.y * w.x;
            s[idx * 16 + tx]        = make_float2(u.x + vr, u.y + vi);
            s[(idx + mh) * 16 + tx] = make_float2(u.x - vr, u.y - vi);
        }
        __syncthreads();
    }
    const float sc = 1.0f / 65536.0f;
    float* FB = (float*)g_FB;
    for (int r = ty; r < 256; r += 64) {
        float val = s[r * 16 + tx].x * sc;
        int n2 = (r ^ 128);
        float* row = FB + (size_t)b * IMG + n2 * 256;
        if (x == 0) {
            row[128] = val;          // column m=0 -> shifted 128 (value ~0)
            row[0]   = 0.0f;         // column m=128 is exactly zero
        } else {
            row[x + 128] = val;      // m=x      -> shifted x+128
            row[128 - x] = -val;     // m=256-x  -> shifted 128-x, negated
        }
    }
}

// Fused 3-conv stack with packed f32x2 complex MACs.
// ADJ=false: REAL input (float buffer), weights (w1,w2,w3), *theta, out g_FA.
// ADJ=true : complex input g_FA, weights (tconj(w3),tconj(w2),tconj(w1)), out g_FB.
template <bool ADJ>
__global__ void __launch_bounds__(512, 2)
fused_stack(const float* __restrict__ inR, const float2* __restrict__ inC,
            float2* __restrict__ out,
            const float* __restrict__ w1r, const float* __restrict__ w1i,
            const float* __restrict__ w2r, const float* __restrict__ w2i,
            const float* __restrict__ w3r, const float* __restrict__ w3i,
            const float* __restrict__ thr, const float* __restrict__ thi,
            const int* __restrict__ ep, int iter) {
    if (iter >= get_K(ep)) return;
    extern __shared__ char smc[];
    float*      INr  = (float*)smc;                        // 1444 floats (!ADJ)
    float2*     INc  = (float2*)smc;                       // 1444 float2 (ADJ)
    float2*     T1   = (float2*)(smc + 11552);             // 5184 float2
    ulonglong2* Wb   = (ulonglong2*)(smc + 11552 + 41472); // 144
    u64*        Wa01 = (u64*)(smc + 11552 + 41472 + 2304); // 36
    u64*        Wa23 = Wa01 + 36;                          // 36
    ulonglong2* Wc2  = (ulonglong2*)(Wa23 + 36);           // 36

    int b   = blockIdx.z;
    int ox  = blockIdx.x * 32;
    int oy  = blockIdx.y * 32;
    int tid = threadIdx.x;

    // ---- weights ----
    if (tid < 216) {
        if (tid < 144) {            // stage 2
            int u = tid;
            int co = u & 3, tap = (u >> 2) % 9, ci = u / 36;
            float wr, wi;
            if (!ADJ) {
                int j = ((b * 4 + co) * 4 + ci) * 9 + tap;
                wr = w2r[j]; wi = w2i[j];
            } else {
                int tt = (tap % 3) * 3 + tap / 3;
                int j = ((b * 4 + ci) * 4 + co) * 9 + tt;
                wr = w2r[j]; wi = -w2i[j];
            }
            ulonglong2 wv; wv.x = pk2(wr, wi); wv.y = pk2(-wi, wr);
            Wb[(ci * 9 + tap) * 4 + co] = wv;
        } else if (tid < 180) {     // stage 1
            int u = tid - 144;
            int tap = u >> 2, co = u & 3;
            float wr, wi;
            if (!ADJ) {
                int j = (b * 4 + co) * 9 + tap;
                wr = w1r[j]; wi = w1i[j];
            } else {
                int tt = (tap % 3) * 3 + tap / 3;
                int j = (b * 4 + co) * 9 + tt;
                wr = w3r[j]; wi = -w3i[j];
            }
            Wa01[u] = pk2(wr, wi);
            Wa23[u] = pk2(-wi, wr);
        } else {                    // stage 3
            int u = tid - 180;
            int ci = u / 9, tap = u % 9;
            float wr, wi;
            if (!ADJ) {
                int j = (b * 4 + ci) * 9 + tap;
                wr = w3r[j]; wi = w3i[j];
            } else {
                int tt = (tap % 3) * 3 + tap / 3;
                int j = (b * 4 + ci) * 9 + tt;
                wr = w1r[j]; wi = -w1i[j];
            }
            ulonglong2 wv; wv.x = pk2(wr, wi); wv.y = pk2(-wi, wr);
            Wc2[u] = wv;
        }
    }

    // ---- input tile 38x38, zero pad ----
    for (int i = tid; i < 38 * 38; i += 512) {
        int iy = i / 38, ix = i % 38;
        int gy = oy - 3 + iy, gx = ox - 3 + ix;
        bool in = ((unsigned)gy < 256u) && ((unsigned)gx < 256u);
        if (!ADJ) {
            INr[i] = in ? inR[(size_t)b * IMG + gy * 256 + gx] : 0.0f;
        } else {
            INc[i] = in ? inC[(size_t)b * IMG + gy * 256 + gx] : make_float2(0.f, 0.f);
        }
    }
    __syncthreads();

    // ---- stage 1: 1 -> 4 over 36x36 ----
    for (int p = tid; p < 1296; p += 512) {
        int py = p / 36, px = p % 36;
        int gy = oy - 2 + py, gx = ox - 2 + px;
        u64 a0 = 0, a1 = 0, a2 = 0, a3 = 0;
        if ((unsigned)gy < 256u && (unsigned)gx < 256u) {
            int base = py * 38 + px;
#pragma unroll
            for (int tap = 0; tap < 9; ++tap) {
                int off = base + (tap / 3) * 38 + tap % 3;
                if (!ADJ) {
                    float sv = INr[off];
                    u64 va = pk2(sv, sv);
                    cfma(a0, va, Wa01[tap * 4 + 0]);
                    cfma(a1, va, Wa01[tap * 4 + 1]);
                    cfma(a2, va, Wa01[tap * 4 + 2]);
                    cfma(a3, va, Wa01[tap * 4 + 3]);
                } else {
                    float2 v = INc[off];
                    u64 va = pk2(v.x, v.x), vb = pk2(v.y, v.y);
                    cfma(a0, va, Wa01[tap * 4 + 0]); cfma(a0, vb, Wa23[tap * 4 + 0]);
                    cfma(a1, va, Wa01[tap * 4 + 1]); cfma(a1, vb, Wa23[tap * 4 + 1]);
                    cfma(a2, va, Wa01[tap * 4 + 2]); cfma(a2, vb, Wa23[tap * 4 + 2]);
                    cfma(a3, va, Wa01[tap * 4 + 3]); cfma(a3, vb, Wa23[tap * 4 + 3]);
                }
            }
        }
        T1[0 * 1296 + p] = upk(a0);
        T1[1 * 1296 + p] = upk(a1);
        T1[2 * 1296 + p] = upk(a2);
        T1[3 * 1296 + p] = upk(a3);
    }
    __syncthreads();

    // ---- stage 2: 4 -> 4 over 34x34 (f32x2 packed) ----
    {
        u64 acc[3][4];
        int bidx[3];
        bool val[3];
#pragma unroll
        for (int k = 0; k < 3; ++k) {
            int p = tid + k * 512;
            val[k] = p < 1156;
            int pc = val[k] ? p : 1155;
            int py = pc / 34, px = pc - py * 34;
            bidx[k] = py * 36 + px;
#pragma unroll
            for (int c = 0; c < 4; ++c) acc[k][c] = 0;
        }
#pragma unroll
        for (int ci = 0; ci < 4; ++ci) {
            const float2* Tci = T1 + ci * 1296;
#pragma unroll
            for (int tap = 0; tap < 9; ++tap) {
                ulonglong2 w0 = Wb[(ci * 9 + tap) * 4 + 0];
                ulonglong2 w1 = Wb[(ci * 9 + tap) * 4 + 1];
                ulonglong2 w2 = Wb[(ci * 9 + tap) * 4 + 2];
                ulonglong2 w3 = Wb[(ci * 9 + tap) * 4 + 3];
                int off = (tap / 3) * 36 + tap % 3;
#pragma unroll
                for (int k = 0; k < 3; ++k) {
                    float2 v = Tci[bidx[k] + off];
                    u64 va = pk2(v.x, v.x), vb = pk2(v.y, v.y);
                    cfma(acc[k][0], va, w0.x); cfma(acc[k][0], vb, w0.y);
                    cfma(acc[k][1], va, w1.x); cfma(acc[k][1], vb, w1.y);
                    cfma(acc[k][2], va, w2.x); cfma(acc[k][2], vb, w2.y);
                    cfma(acc[k][3], va, w3.x); cfma(acc[k][3], vb, w3.y);
                }
            }
        }
        __syncthreads();   // T1 reads done; overwrite with T2
#pragma unroll
        for (int k = 0; k < 3; ++k) {
            if (val[k]) {
                int p = tid + k * 512;
                int py = p / 34, px = p - py * 34;
                int gy = oy - 1 + py, gx = ox - 1 + px;
                bool in2 = ((unsigned)gy < 256u) && ((unsigned)gx < 256u);
#pragma unroll
                for (int c = 0; c < 4; ++c)
                    T1[c * 1156 + p] = in2 ? upk(acc[k][c]) : make_float2(0.f, 0.f);
            }
        }
    }
    __syncthreads();

    // ---- stage 3: 4 -> 1 over 32x32 ----
    {
        u64 acc[2];
        int bidx[2];
#pragma unroll
        for (int k = 0; k < 2; ++k) {
            int p = tid + k * 512;
            int py = p >> 5, px = p & 31;
            bidx[k] = py * 34 + px;
            acc[k] = 0;
        }
#pragma unroll
        for (int ci = 0; ci < 4; ++ci) {
            const float2* Tci = T1 + ci * 1156;
#pragma unroll
            for (int tap = 0; tap < 9; ++tap) {
                ulonglong2 w = Wc2[ci * 9 + tap];
                int off = (tap / 3) * 34 + tap % 3;
#pragma unroll
                for (int k = 0; k < 2; ++k) {
                    float2 v = Tci[bidx[k] + off];
                    cfma(acc[k], pk2(v.x, v.x), w.x);
                    cfma(acc[k], pk2(v.y, v.y), w.y);
                }
            }
        }
        float2* ob = out + (size_t)b * IMG;
#pragma unroll
        for (int k = 0; k < 2; ++k) {
            int p = tid + k * 512;
            int py = p >> 5, px = p & 31;
            int gidx = (oy + py) * 256 + (ox + px);
            float2 a = upk(acc[k]);
            if (!ADJ) {
                float tr = thr[b * IMG + gidx], ti = thi[b * IMG + gidx];
                u64 r = 0;
                cfma(r, pk2(a.x, a.x), pk2(tr, ti));
                cfma(r, pk2(a.y, a.y), pk2(-ti, tr));
                a = upk(r);
            }
            ob[gidx] = a;
        }
    }
}

// fft2 pass 1: ifftshift on read, forward FFT along x. 4 rows/block.
__global__ void __launch_bounds__(512)
fft_row_fwd(const int* __restrict__ ep, int iter) {
    if (iter >= get_K(ep)) return;
    __shared__ float2 s[4][256];
    __shared__ float2 tw[128];
    int b = blockIdx.y, t = threadIdx.x, ty = threadIdx.y;
    int y = blockIdx.x * 4 + ty;
    build_tw(tw, ty * 128 + t, -1.0f);
    const float2* irow = g_FB + (b * 256 + (y ^ 128)) * 256;
#pragma unroll
    for (int k = 0; k < 2; ++k) {
        int p = t + k * 128;
        s[ty][rev8(p)] = irow[p ^ 128];
    }
    __syncthreads();
    fft256_ip(s[ty], tw, t);
    float2* orow = g_FA + (b * 256 + y) * 256;
    orow[t]       = s[ty][t];
    orow[t + 128] = s[ty][t + 128];
}

// fft2 pass 2: 16-col tiles, crop 127x127, accumulate into x.
__global__ void __launch_bounds__(1024)
fft_col_fwd_accum(const int* __restrict__ ep, int iter) {
    if (iter >= get_K(ep)) return;
    __shared__ float2 s[256 * 16];
    __shared__ float2 tw[128];
    int b  = blockIdx.y;
    int tx = threadIdx.x, ty = threadIdx.y;
    int tid = ty * 16 + tx;
    int x = blockIdx.x * 16 + tx;
    build_tw(tw, tid, -1.0f);
    for (int r = ty; r < 256; r += 64)
        s[rev8(r) * 16 + tx] = g_FA[(b * 256 + r) * 256 + x];
    __syncthreads();
#pragma unroll
    for (int st = 1; st <= 8; ++st) {
        int mh = 1 << (st - 1);
#pragma unroll
        for (int k = 0; k < 2; ++k) {
            int i   = ty + 64 * k;
            int idx = ((i >> (st - 1)) << st) | (i & (mh - 1));
            int twi = (i & (mh - 1)) << (8 - st);
            float2 w = tw[twi];
            float2 u = s[idx * 16 + tx];
            float2 v = s[(idx + mh) * 16 + tx];
            float vr = v.x * w.x - v.y * w.y;
            float vi = v.x * w.y + v.y * w.x;
            s[idx * 16 + tx]        = make_float2(u.x + vr, u.y + vi);
            s[(idx + mh) * 16 + tx] = make_float2(u.x - vr, u.y - vi);
        }
        __syncthreads();
    }
    if (x < 127) {
        for (int r = ty; r < 127; r += 64)
            g_x[b * NN + r * 127 + x] += s[r * 16 + tx].x;
    }
}

// Residual norm: division-free indexing, 2 rows per block.
__global__ void __launch_bounds__(256)
norm_partial(const float* __restrict__ f, const float* __restrict__ kA) {
    __shared__ float sr_s[256], sf_s[256];
    int b = blockIdx.y;
    int row = blockIdx.x * 2 + (threadIdx.x >> 7);
    int col = threadIdx.x & 127;
    float sr = 0.0f, sf = 0.0f;
    if (row < 127 && col < 127) {
        int p = row * 127 + col;
        const float* ka = kA + b * 9;
        const float* xb = g_x + b * NN;
        float s = 0.0f;
        if (row > 0) {
            if (col > 0)   s += ka[0] * xb[p - 128];
            s += ka[1] * xb[p - 127];
            if (col < 126) s += ka[2] * xb[p - 126];
        }
        if (col > 0)   s += ka[3] * xb[p - 1];
        s += ka[4] * xb[p];
        if (col < 126) s += ka[5] * xb[p + 1];
        if (row < 126) {
            if (col > 0)   s += ka[6] * xb[p + 126];
            s += ka[7] * xb[p + 127];
            if (col < 126) s += ka[8] * xb[p + 128];
        }
        float fv = f[b * NN + p];
        float rv = fv - s;
        sr = rv * rv;
        sf = fv * fv;
    }
    sr_s[threadIdx.x] = sr;
    sf_s[threadIdx.x] = sf;
    __syncthreads();
    for (int o = 128; o > 0; o >>= 1) {
        if (threadIdx.x < o) {
            sr_s[threadIdx.x] += sr_s[threadIdx.x + o];
            sf_s[threadIdx.x] += sf_s[threadIdx.x + o];
        }
        __syncthreads();
    }
    if (threadIdx.x == 0) g_part[b * 64 + blockIdx.x] = make_float2(sr_s[0], sf_s[0]);
}

__global__ void norm_final(float* __restrict__ out) {
    __shared__ float sr_s[256], sf_s[256];
    float sr = 0.0f, sf = 0.0f;
#pragma unroll
    for (int k = 0; k < 4; ++k) {
        float2 v = g_part[threadIdx.x + k * 256];
        sr += v.x; sf += v.y;
    }
    sr_s[threadIdx.x] = sr;
    sf_s[threadIdx.x] = sf;
    __syncthreads();
    for (int o = 128; o > 0; o >>= 1) {
        if (threadIdx.x < o) {
            sr_s[threadIdx.x] += sr_s[threadIdx.x + o];
            sf_s[threadIdx.x] += sf_s[threadIdx.x + o];
        }
        __syncthreads();
    }
    if (threadIdx.x == 0) out[0] = sqrtf(sr_s[0] / sf_s[0]);
}

// ---------------- launch ------------------------------------------------------
extern "C" void kernel_launch(void* const* d_in, const int* in_sizes, int n_in,
                              void* d_out, int out_size) {
    (void)in_sizes; (void)n_in; (void)out_size;
    const float* f   = (const float*)d_in[0];
    const float* kA  = (const float*)d_in[1];
    const float* w1r = (const float*)d_in[2];
    const float* w1i = (const float*)d_in[3];
    const float* w2r = (const float*)d_in[4];
    const float* w2i = (const float*)d_in[5];
    const float* w3r = (const float*)d_in[6];
    const float* w3i = (const float*)d_in[7];
    const float* thr = (const float*)d_in[8];
    const float* thi = (const float*)d_in[9];
    const int*   ep  = (const int*)d_in[10];
    float* out = (float*)d_out;

    void *pFA = nullptr, *pFB = nullptr;
    cudaGetSymbolAddress(&pFA, g_FA);
    cudaGetSymbolAddress(&pFB, g_FB);

    const int FSM = 11552 + 41472 + 2304 + 288 + 288 + 576;   // 56480 B
    cudaFuncSetAttribute(fused_stack<false>, cudaFuncAttributeMaxDynamicSharedMemorySize, FSM);
    cudaFuncSetAttribute(fused_stack<true>,  cudaFuncAttributeMaxDynamicSharedMemorySize, FSM);

    dim3 jg(4, 4, NB);
    for (int it = 0; it < 3; ++it) {
        jacobi_tile<<<jg, 512>>>(f, kA, ep, it, 0, it == 0 ? 1 : 0);
        jacobi_tile<<<jg, 512>>>(f, kA, ep, it, 1, 0);
        fft_row_expand<<<dim3(32, NB), dim3(128, 4)>>>(ep, it);
        fft_col_inv<<<dim3(8, NB), dim3(16, 64)>>>(ep, it);
        fused_stack<false><<<dim3(8, 8, NB), 512, FSM>>>(
            (const float*)pFB, nullptr, (float2*)pFA,
            w1r, w1i, w2r, w2i, w3r, w3i, thr, thi, ep, it);
        fused_stack<true><<<dim3(8, 8, NB), 512, FSM>>>(
            nullptr, (const float2*)pFA, (float2*)pFB,
            w1r, w1i, w2r, w2i, w3r, w3i, nullptr, nullptr, ep, it);
        fft_row_fwd<<<dim3(64, NB), dim3(128, 4)>>>(ep, it);
        fft_col_fwd_accum<<<dim3(8, NB), dim3(16, 64)>>>(ep, it);
    }

    norm_partial<<<dim3(64, NB), 256>>>(f, kA);
    norm_final<<<1, 256>>>(out);
}

// round 8
// speedup vs baseline: 1.5944x; 1.0332x over previous
#include <cuda_runtime.h>
#include <math.h>

#define NB   16
#define NI   127
#define NN   16129      // 127*127
#define IMG  65536      // 256*256
#define TS   32
#define HL2  11
#define LT2  54         // TS + 2*HL2
#define LTN  2916       // LT2*LT2

typedef unsigned long long u64;

// ---------------- scratch (static device globals) ----------------------------
static __device__ float  g_x[NB * NN];
static __device__ float  g_r[NB * NN];
static __device__ float2 g_FA[NB * IMG];
static __device__ float2 g_FB[NB * IMG];   // also reused as float (real) buffer
static __device__ float2 g_part[1024];

// ---------------- packed f32x2 helpers ---------------------------------------
__device__ __forceinline__ u64 pk2(float lo, float hi) {
    u64 r; asm("mov.b64 %0, {%1, %2};" : "=l"(r) : "f"(lo), "f"(hi)); return r;
}
__device__ __forceinline__ float2 upk(u64 v) {
    float2 r; asm("mov.b64 {%0, %1}, %2;" : "=f"(r.x), "=f"(r.y) : "l"(v)); return r;
}
__device__ __forceinline__ void cfma(u64& acc, u64 a, u64 b) {
    asm("fma.rn.f32x2 %0, %1, %2, %0;" : "+l"(acc) : "l"(a), "l"(b));
}

// ---------------- misc helpers ------------------------------------------------
__device__ __forceinline__ int get_K(const int* ep) {
    int ei = *ep;
    int e;
    if (ei > 0 && ei <= 1000000) {
        e = ei;
    } else {
        float ff = __int_as_float(ei);
        e = (ff >= 1.0f && ff <= 1000000.0f) ? (int)ff : 120;
    }
    int K = (e - 1) / 40 + 1;
    if (K > 10) K = 10;
    if (K < 1)  K = 1;
    return K;
}

// base-4 digit reversal of 8-bit index
__device__ __forceinline__ int dr4(int p) {
    return ((p & 3) << 6) | (((p >> 2) & 3) << 4) | (((p >> 4) & 3) << 2) | ((p >> 6) & 3);
}

__device__ __forceinline__ float2 cmulf(float2 a, float2 b) {
    return make_float2(a.x * b.x - a.y * b.y, a.x * b.y + a.y * b.x);
}

// Build 192-entry twiddle table: tw[k] = exp(sign * 2*pi*i * k / 256)
__device__ __forceinline__ void build_tw(float2* tw, int tid, float sign) {
    if (tid < 192) {
        float s, c;
        __sincosf(sign * 6.283185307179586f * (float)tid * (1.0f / 256.0f), &s, &c);
        tw[tid] = make_float2(c, s);
    }
}

// Radix-4 256-pt DIT FFT, input base-4 digit-reversed, output natural.
// 64 butterflies/stage, t in 0..63 handles one; 4 stages.
// SGN = +1 inverse / -1 forward (must match tw table sign).
template <int STRIDE, int SGN>
__device__ __forceinline__ void fft256_r4(float2* s, const float2* tw, int t) {
#pragma unroll
    for (int st = 0; st < 4; ++st) {
        int L    = 1 << (2 * st);
        int k    = t & (L - 1);
        int g    = t >> (2 * st);
        int i0   = g * 4 * L + k;
        int step = 64 >> (2 * st);
        float2 a = s[i0 * STRIDE];
        float2 b = s[(i0 + L) * STRIDE];
        float2 c = s[(i0 + 2 * L) * STRIDE];
        float2 d = s[(i0 + 3 * L) * STRIDE];
        b = cmulf(b, tw[k * step]);
        c = cmulf(c, tw[2 * k * step]);
        d = cmulf(d, tw[3 * k * step]);
        float2 t0 = make_float2(a.x + c.x, a.y + c.y);
        float2 t1 = make_float2(a.x - c.x, a.y - c.y);
        float2 t2 = make_float2(b.x + d.x, b.y + d.y);
        float2 t3 = make_float2(b.x - d.x, b.y - d.y);
        float2 rot = make_float2(-(float)SGN * t3.y, (float)SGN * t3.x);   // SGN*i*t3
        s[i0 * STRIDE]           = make_float2(t0.x + t2.x, t0.y + t2.y);
        s[(i0 + L) * STRIDE]     = make_float2(t1.x + rot.x, t1.y + rot.y);
        s[(i0 + 2 * L) * STRIDE] = make_float2(t0.x - t2.x, t0.y - t2.y);
        s[(i0 + 3 * L) * STRIDE] = make_float2(t1.x - rot.x, t1.y - rot.y);
        __syncthreads();
    }
}

// ---------------- kernels ----------------------------------------------------
// Sweep-chunked Jacobi: 10 sweeps/launch on 54x54 tiles (halo 11), 512 threads.
__global__ void __launch_bounds__(512)
jacobi_tile(const float* __restrict__ f, const float* __restrict__ kA,
            const int* __restrict__ ep, int iter, int final_, int zero) {
    if (iter >= get_K(ep)) return;
    __shared__ float xs0[LTN], xs1[LTN], fs[LTN];
    int b  = blockIdx.z;
    int ox = blockIdx.x * TS - HL2;
    int oy = blockIdx.y * TS - HL2;
    int tid = threadIdx.x;
    const float* ka = kA + b * 9;
    float k0 = ka[0], k1 = ka[1], k2 = ka[2], k3 = ka[3], k4 = ka[4];
    float k5 = ka[5], k6 = ka[6], k7 = ka[7], k8 = ka[8];
    float tau = 0.5f / k4;

    int  iyk[6], ixk[6];
    bool okk[6], domk[6];
#pragma unroll
    for (int k = 0; k < 6; ++k) {
        int p = tid + k * 512;
        bool ok = p < LTN;
        int iy = 0, ix = 0;
        if (ok) { iy = p / LT2; ix = p - iy * LT2; }
        int gy = oy + iy, gx = ox + ix;
        bool dom = ok && ((unsigned)gy < 127u) && ((unsigned)gx < 127u);
        if (ok) {
            xs0[p] = (dom && !zero) ? g_x[b * NN + gy * 127 + gx] : 0.0f;
            fs[p]  = dom ? f[b * NN + gy * 127 + gx] : 0.0f;
        }
        iyk[k] = iy; ixk[k] = ix; okk[k] = ok; domk[k] = dom;
    }
    __syncthreads();

    float* cur = xs0;
    float* nxt = xs1;
#pragma unroll
    for (int s = 0; s < 10; ++s) {
        int a = s + 1;
#pragma unroll
        for (int k = 0; k < 6; ++k) {
            if (okk[k]) {
                int p = tid + k * 512;
                float nv = cur[p];
                int iy = iyk[k], ix = ixk[k];
                if (domk[k] && iy >= a && iy < LT2 - a && ix >= a && ix < LT2 - a) {
                    float ax = k0 * cur[p - LT2 - 1] + k1 * cur[p - LT2] + k2 * cur[p - LT2 + 1]
                             + k3 * cur[p - 1]       + k4 * cur[p]       + k5 * cur[p + 1]
                             + k6 * cur[p + LT2 - 1] + k7 * cur[p + LT2] + k8 * cur[p + LT2 + 1];
                    nv = cur[p] + tau * (fs[p] - ax);
                }
                nxt[p] = nv;
            }
        }
        __syncthreads();
        float* tsw = cur; cur = nxt; nxt = tsw;
    }

#pragma unroll
    for (int k = 0; k < 2; ++k) {
        int p2 = tid + k * 512;
        int py = p2 >> 5, px = p2 & 31;
        int iy = HL2 + py, ix = HL2 + px;
        int gy = oy + iy, gx = ox + ix;
        if (((unsigned)gy < 127u) && ((unsigned)gx < 127u)) {
            int i = iy * LT2 + ix;
            g_x[b * NN + gy * 127 + gx] = cur[i];
            if (final_) {
                float ax = k0 * cur[i - LT2 - 1] + k1 * cur[i - LT2] + k2 * cur[i - LT2 + 1]
                         + k3 * cur[i - 1]       + k4 * cur[i]       + k5 * cur[i + 1]
                         + k6 * cur[i + LT2 - 1] + k7 * cur[i + LT2] + k8 * cur[i + LT2 + 1];
                g_r[b * NN + gy * 127 + gx] = fs[i] - ax;
            }
        }
    }
}

// ifft2 pass 1 (odd symmetry): FFT rows 1..127; store only k=0..127.
// Block (64,8): 8 rows/block, radix-4.
__global__ void __launch_bounds__(512)
fft_row_expand(const int* __restrict__ ep, int iter) {
    if (iter >= get_K(ep)) return;
    __shared__ float2 s[8][256];
    __shared__ float2 tw[192];
    int b = blockIdx.y, t = threadIdx.x, ty = threadIdx.y;
    int y = blockIdx.x * 8 + ty + 1;            // 1..128 (128 invalid)
    bool ok = (y <= 127);
    build_tw(tw, ty * 64 + t, 1.0f);
    const float* rrow = g_r + (b * NN + (ok ? (y - 1) : 0) * 127);
#pragma unroll
    for (int k = 0; k < 4; ++k) {
        int p = t + k * 64;
        float v = 0.0f;
        if (ok) {
            if (p >= 1 && p <= 127)  v =  rrow[p - 1];
            else if (p >= 129)       v = -rrow[255 - p];
        }
        s[ty][dr4(p)] = make_float2(v, 0.0f);
    }
    __syncthreads();
    fft256_r4<1, 1>(s[ty], tw, t);
    if (ok) {
        float2* base = g_FA + (size_t)b * IMG;
#pragma unroll
        for (int k = 0; k < 2; ++k) {
            int kk = t + k * 64;                // 0..127
            float2 v0 = s[ty][kk];
            base[y * 256 + kk]         = v0;
            base[(256 - y) * 256 + kk] = make_float2(-v0.x, -v0.y);
            if (y == 1) {
                base[kk]             = make_float2(0.f, 0.f);
                base[128 * 256 + kk] = make_float2(0.f, 0.f);
            }
        }
    }
}

// ifft2 pass 2: columns 0..127; output purely REAL; radix-4, block (16,64).
__global__ void __launch_bounds__(1024)
fft_col_inv(const int* __restrict__ ep, int iter) {
    if (iter >= get_K(ep)) return;
    __shared__ float2 s[256 * 16];
    __shared__ float2 tw[192];
    int b  = blockIdx.y;
    int tx = threadIdx.x, ty = threadIdx.y;     // 16 x 64
    int tid = ty * 16 + tx;
    int x = blockIdx.x * 16 + tx;               // 0..127
    build_tw(tw, tid, 1.0f);
#pragma unroll
    for (int k = 0; k < 4; ++k) {
        int r = ty + k * 64;
        s[dr4(r) * 16 + tx] = g_FA[(b * 256 + r) * 256 + x];
    }
    __syncthreads();
    fft256_r4<16, 1>(s + tx, tw, ty);
    const float sc = 1.0f / 65536.0f;
    float* FB = (float*)g_FB;
#pragma unroll
    for (int k = 0; k < 4; ++k) {
        int r = ty + k * 64;
        float val = s[r * 16 + tx].x * sc;
        int n2 = (r ^ 128);
        float* row = FB + (size_t)b * IMG + n2 * 256;
        if (x == 0) {
            row[128] = val;
            row[0]   = 0.0f;
        } else {
            row[x + 128] = val;
            row[128 - x] = -val;
        }
    }
}

// Fused 3-conv stack with packed f32x2 complex MACs.
template <bool ADJ>
__global__ void __launch_bounds__(512, 2)
fused_stack(const float* __restrict__ inR, const float2* __restrict__ inC,
            float2* __restrict__ out,
            const float* __restrict__ w1r, const float* __restrict__ w1i,
            const float* __restrict__ w2r, const float* __restrict__ w2i,
            const float* __restrict__ w3r, const float* __restrict__ w3i,
            const float* __restrict__ thr, const float* __restrict__ thi,
            const int* __restrict__ ep, int iter) {
    if (iter >= get_K(ep)) return;
    extern __shared__ char smc[];
    float*      INr  = (float*)smc;                        // 1444 floats (!ADJ)
    float2*     INc  = (float2*)smc;                       // 1444 float2 (ADJ)
    float2*     T1   = (float2*)(smc + 11552);             // 5184 float2
    ulonglong2* Wb   = (ulonglong2*)(smc + 11552 + 41472); // 144
    u64*        Wa01 = (u64*)(smc + 11552 + 41472 + 2304); // 36
    u64*        Wa23 = Wa01 + 36;                          // 36
    ulonglong2* Wc2  = (ulonglong2*)(Wa23 + 36);           // 36

    int b   = blockIdx.z;
    int ox  = blockIdx.x * 32;
    int oy  = blockIdx.y * 32;
    int tid = threadIdx.x;

    if (tid < 216) {
        if (tid < 144) {
            int u = tid;
            int co = u & 3, tap = (u >> 2) % 9, ci = u / 36;
            float wr, wi;
            if (!ADJ) {
                int j = ((b * 4 + co) * 4 + ci) * 9 + tap;
                wr = w2r[j]; wi = w2i[j];
            } else {
                int tt = (tap % 3) * 3 + tap / 3;
                int j = ((b * 4 + ci) * 4 + co) * 9 + tt;
                wr = w2r[j]; wi = -w2i[j];
            }
            ulonglong2 wv; wv.x = pk2(wr, wi); wv.y = pk2(-wi, wr);
            Wb[(ci * 9 + tap) * 4 + co] = wv;
        } else if (tid < 180) {
            int u = tid - 144;
            int tap = u >> 2, co = u & 3;
            float wr, wi;
            if (!ADJ) {
                int j = (b * 4 + co) * 9 + tap;
                wr = w1r[j]; wi = w1i[j];
            } else {
                int tt = (tap % 3) * 3 + tap / 3;
                int j = (b * 4 + co) * 9 + tt;
                wr = w3r[j]; wi = -w3i[j];
            }
            Wa01[u] = pk2(wr, wi);
            Wa23[u] = pk2(-wi, wr);
        } else {
            int u = tid - 180;
            int ci = u / 9, tap = u % 9;
            float wr, wi;
            if (!ADJ) {
                int j = (b * 4 + ci) * 9 + tap;
                wr = w3r[j]; wi = w3i[j];
            } else {
                int tt = (tap % 3) * 3 + tap / 3;
                int j = (b * 4 + ci) * 9 + tt;
                wr = w1r[j]; wi = -w1i[j];
            }
            ulonglong2 wv; wv.x = pk2(wr, wi); wv.y = pk2(-wi, wr);
            Wc2[u] = wv;
        }
    }

    for (int i = tid; i < 38 * 38; i += 512) {
        int iy = i / 38, ix = i % 38;
        int gy = oy - 3 + iy, gx = ox - 3 + ix;
        bool in = ((unsigned)gy < 256u) && ((unsigned)gx < 256u);
        if (!ADJ) {
            INr[i] = in ? inR[(size_t)b * IMG + gy * 256 + gx] : 0.0f;
        } else {
            INc[i] = in ? inC[(size_t)b * IMG + gy * 256 + gx] : make_float2(0.f, 0.f);
        }
    }
    __syncthreads();

    // stage 1: 1 -> 4 over 36x36
    for (int p = tid; p < 1296; p += 512) {
        int py = p / 36, px = p % 36;
        int gy = oy - 2 + py, gx = ox - 2 + px;
        u64 a0 = 0, a1 = 0, a2 = 0, a3 = 0;
        if ((unsigned)gy < 256u && (unsigned)gx < 256u) {
            int base = py * 38 + px;
#pragma unroll
            for (int tap = 0; tap < 9; ++tap) {
                int off = base + (tap / 3) * 38 + tap % 3;
                if (!ADJ) {
                    float sv = INr[off];
                    u64 va = pk2(sv, sv);
                    cfma(a0, va, Wa01[tap * 4 + 0]);
                    cfma(a1, va, Wa01[tap * 4 + 1]);
                    cfma(a2, va, Wa01[tap * 4 + 2]);
                    cfma(a3, va, Wa01[tap * 4 + 3]);
                } else {
                    float2 v = INc[off];
                    u64 va = pk2(v.x, v.x), vb = pk2(v.y, v.y);
                    cfma(a0, va, Wa01[tap * 4 + 0]); cfma(a0, vb, Wa23[tap * 4 + 0]);
                    cfma(a1, va, Wa01[tap * 4 + 1]); cfma(a1, vb, Wa23[tap * 4 + 1]);
                    cfma(a2, va, Wa01[tap * 4 + 2]); cfma(a2, vb, Wa23[tap * 4 + 2]);
                    cfma(a3, va, Wa01[tap * 4 + 3]); cfma(a3, vb, Wa23[tap * 4 + 3]);
                }
            }
        }
        T1[0 * 1296 + p] = upk(a0);
        T1[1 * 1296 + p] = upk(a1);
        T1[2 * 1296 + p] = upk(a2);
        T1[3 * 1296 + p] = upk(a3);
    }
    __syncthreads();

    // stage 2: 4 -> 4 over 34x34
    {
        u64 acc[3][4];
        int bidx[3];
        bool val[3];
#pragma unroll
        for (int k = 0; k < 3; ++k) {
            int p = tid + k * 512;
            val[k] = p < 1156;
            int pc = val[k] ? p : 1155;
            int py = pc / 34, px = pc - py * 34;
            bidx[k] = py * 36 + px;
#pragma unroll
            for (int c = 0; c < 4; ++c) acc[k][c] = 0;
        }
#pragma unroll
        for (int ci = 0; ci < 4; ++ci) {
            const float2* Tci = T1 + ci * 1296;
#pragma unroll
            for (int tap = 0; tap < 9; ++tap) {
                ulonglong2 w0 = Wb[(ci * 9 + tap) * 4 + 0];
                ulonglong2 w1 = Wb[(ci * 9 + tap) * 4 + 1];
                ulonglong2 w2 = Wb[(ci * 9 + tap) * 4 + 2];
                ulonglong2 w3 = Wb[(ci * 9 + tap) * 4 + 3];
                int off = (tap / 3) * 36 + tap % 3;
#pragma unroll
                for (int k = 0; k < 3; ++k) {
                    float2 v = Tci[bidx[k] + off];
                    u64 va = pk2(v.x, v.x), vb = pk2(v.y, v.y);
                    cfma(acc[k][0], va, w0.x); cfma(acc[k][0], vb, w0.y);
                    cfma(acc[k][1], va, w1.x); cfma(acc[k][1], vb, w1.y);
                    cfma(acc[k][2], va, w2.x); cfma(acc[k][2], vb, w2.y);
                    cfma(acc[k][3], va, w3.x); cfma(acc[k][3], vb, w3.y);
                }
            }
        }
        __syncthreads();
#pragma unroll
        for (int k = 0; k < 3; ++k) {
            if (val[k]) {
                int p = tid + k * 512;
                int py = p / 34, px = p - py * 34;
                int gy = oy - 1 + py, gx = ox - 1 + px;
                bool in2 = ((unsigned)gy < 256u) && ((unsigned)gx < 256u);
#pragma unroll
                for (int c = 0; c < 4; ++c)
                    T1[c * 1156 + p] = in2 ? upk(acc[k][c]) : make_float2(0.f, 0.f);
            }
        }
    }
    __syncthreads();

    // stage 3: 4 -> 1 over 32x32
    {
        u64 acc[2];
        int bidx[2];
#pragma unroll
        for (int k = 0; k < 2; ++k) {
            int p = tid + k * 512;
            int py = p >> 5, px = p & 31;
            bidx[k] = py * 34 + px;
            acc[k] = 0;
        }
#pragma unroll
        for (int ci = 0; ci < 4; ++ci) {
            const float2* Tci = T1 + ci * 1156;
#pragma unroll
            for (int tap = 0; tap < 9; ++tap) {
                ulonglong2 w = Wc2[ci * 9 + tap];
                int off = (tap / 3) * 34 + tap % 3;
#pragma unroll
                for (int k = 0; k < 2; ++k) {
                    float2 v = Tci[bidx[k] + off];
                    cfma(acc[k], pk2(v.x, v.x), w.x);
                    cfma(acc[k], pk2(v.y, v.y), w.y);
                }
            }
        }
        float2* ob = out + (size_t)b * IMG;
#pragma unroll
        for (int k = 0; k < 2; ++k) {
            int p = tid + k * 512;
            int py = p >> 5, px = p & 31;
            int gidx = (oy + py) * 256 + (ox + px);
            float2 a = upk(acc[k]);
            if (!ADJ) {
                float tr = thr[b * IMG + gidx], ti = thi[b * IMG + gidx];
                u64 r = 0;
                cfma(r, pk2(a.x, a.x), pk2(tr, ti));
                cfma(r, pk2(a.y, a.y), pk2(-ti, tr));
                a = upk(r);
            }
            ob[gidx] = a;
        }
    }
}

// fft2 pass 1: ifftshift on read, forward FFT along x; store k=0..127 only.
// Block (64,8), radix-4.
__global__ void __launch_bounds__(512)
fft_row_fwd(const int* __restrict__ ep, int iter) {
    if (iter >= get_K(ep)) return;
    __shared__ float2 s[8][256];
    __shared__ float2 tw[192];
    int b = blockIdx.y, t = threadIdx.x, ty = threadIdx.y;
    int y = blockIdx.x * 8 + ty;
    build_tw(tw, ty * 64 + t, -1.0f);
    const float2* irow = g_FB + (b * 256 + (y ^ 128)) * 256;
#pragma unroll
    for (int k = 0; k < 4; ++k) {
        int p = t + k * 64;
        s[ty][dr4(p)] = irow[p ^ 128];
    }
    __syncthreads();
    fft256_r4<1, -1>(s[ty], tw, t);
    float2* orow = g_FA + (b * 256 + y) * 256;
    orow[t]      = s[ty][t];
    orow[t + 64] = s[ty][t + 64];
}

// fft2 pass 2: columns 0..127, radix-4 block (16,64), crop 127x127, accumulate.
__global__ void __launch_bounds__(1024)
fft_col_fwd_accum(const int* __restrict__ ep, int iter) {
    if (iter >= get_K(ep)) return;
    __shared__ float2 s[256 * 16];
    __shared__ float2 tw[192];
    int b  = blockIdx.y;
    int tx = threadIdx.x, ty = threadIdx.y;
    int tid = ty * 16 + tx;
    int x = blockIdx.x * 16 + tx;
    build_tw(tw, tid, -1.0f);
#pragma unroll
    for (int k = 0; k < 4; ++k) {
        int r = ty + k * 64;
        s[dr4(r) * 16 + tx] = g_FA[(b * 256 + r) * 256 + x];
    }
    __syncthreads();
    fft256_r4<16, -1>(s + tx, tw, ty);
    if (x < 127) {
#pragma unroll
        for (int k = 0; k < 4; ++k) {
            int r = ty + k * 64;
            if (r < 127)
                g_x[b * NN + r * 127 + x] += s[r * 16 + tx].x;
        }
    }
}

// Residual norm.
__global__ void __launch_bounds__(256)
norm_partial(const float* __restrict__ f, const float* __restrict__ kA) {
    __shared__ float sr_s[256], sf_s[256];
    int b = blockIdx.y;
    int row = blockIdx.x * 2 + (threadIdx.x >> 7);
    int col = threadIdx.x & 127;
    float sr = 0.0f, sf = 0.0f;
    if (row < 127 && col < 127) {
        int p = row * 127 + col;
        const float* ka = kA + b * 9;
        const float* xb = g_x + b * NN;
        float s = 0.0f;
        if (row > 0) {
            if (col > 0)   s += ka[0] * xb[p - 128];
            s += ka[1] * xb[p - 127];
            if (col < 126) s += ka[2] * xb[p - 126];
        }
        if (col > 0)   s += ka[3] * xb[p - 1];
        s += ka[4] * xb[p];
        if (col < 126) s += ka[5] * xb[p + 1];
        if (row < 126) {
            if (col > 0)   s += ka[6] * xb[p + 126];
            s += ka[7] * xb[p + 127];
            if (col < 126) s += ka[8] * xb[p + 128];
        }
        float fv = f[b * NN + p];
        float rv = fv - s;
        sr = rv * rv;
        sf = fv * fv;
    }
    sr_s[threadIdx.x] = sr;
    sf_s[threadIdx.x] = sf;
    __syncthreads();
    for (int o = 128; o > 0; o >>= 1) {
        if (threadIdx.x < o) {
            sr_s[threadIdx.x] += sr_s[threadIdx.x + o];
            sf_s[threadIdx.x] += sf_s[threadIdx.x + o];
        }
        __syncthreads();
    }
    if (threadIdx.x == 0) g_part[b * 64 + blockIdx.x] = make_float2(sr_s[0], sf_s[0]);
}

__global__ void norm_final(float* __restrict__ out) {
    __shared__ float sr_s[256], sf_s[256];
    float sr = 0.0f, sf = 0.0f;
#pragma unroll
    for (int k = 0; k < 4; ++k) {
        float2 v = g_part[threadIdx.x + k * 256];
        sr += v.x; sf += v.y;
    }
    sr_s[threadIdx.x] = sr;
    sf_s[threadIdx.x] = sf;
    __syncthreads();
    for (int o = 128; o > 0; o >>= 1) {
        if (threadIdx.x < o) {
            sr_s[threadIdx.x] += sr_s[threadIdx.x + o];
            sf_s[threadIdx.x] += sf_s[threadIdx.x + o];
        }
        __syncthreads();
    }
    if (threadIdx.x == 0) out[0] = sqrtf(sr_s[0] / sf_s[0]);
}

// ---------------- launch ------------------------------------------------------
extern "C" void kernel_launch(void* const* d_in, const int* in_sizes, int n_in,
                              void* d_out, int out_size) {
    (void)in_sizes; (void)n_in; (void)out_size;
    const float* f   = (const float*)d_in[0];
    const float* kA  = (const float*)d_in[1];
    const float* w1r = (const float*)d_in[2];
    const float* w1i = (const float*)d_in[3];
    const float* w2r = (const float*)d_in[4];
    const float* w2i = (const float*)d_in[5];
    const float* w3r = (const float*)d_in[6];
    const float* w3i = (const float*)d_in[7];
    const float* thr = (const float*)d_in[8];
    const float* thi = (const float*)d_in[9];
    const int*   ep  = (const int*)d_in[10];
    float* out = (float*)d_out;

    void *pFA = nullptr, *pFB = nullptr;
    cudaGetSymbolAddress(&pFA, g_FA);
    cudaGetSymbolAddress(&pFB, g_FB);

    const int FSM = 11552 + 41472 + 2304 + 288 + 288 + 576;   // 56480 B
    cudaFuncSetAttribute(fused_stack<false>, cudaFuncAttributeMaxDynamicSharedMemorySize, FSM);
    cudaFuncSetAttribute(fused_stack<true>,  cudaFuncAttributeMaxDynamicSharedMemorySize, FSM);

    dim3 jg(4, 4, NB);
    for (int it = 0; it < 3; ++it) {
        jacobi_tile<<<jg, 512>>>(f, kA, ep, it, 0, it == 0 ? 1 : 0);
        jacobi_tile<<<jg, 512>>>(f, kA, ep, it, 1, 0);
        fft_row_expand<<<dim3(16, NB), dim3(64, 8)>>>(ep, it);
        fft_col_inv<<<dim3(8, NB), dim3(16, 64)>>>(ep, it);
        fused_stack<false><<<dim3(8, 8, NB), 512, FSM>>>(
            (const float*)pFB, nullptr, (float2*)pFA,
            w1r, w1i, w2r, w2i, w3r, w3i, thr, thi, ep, it);
        fused_stack<true><<<dim3(8, 8, NB), 512, FSM>>>(
            nullptr, (const float2*)pFA, (float2*)pFB,
            w1r, w1i, w2r, w2i, w3r, w3i, nullptr, nullptr, ep, it);
        fft_row_fwd<<<dim3(32, NB), dim3(64, 8)>>>(ep, it);
        fft_col_fwd_accum<<<dim3(8, NB), dim3(16, 64)>>>(ep, it);
    }

    norm_partial<<<dim3(64, NB), 256>>>(f, kA);
    norm_final<<<1, 256>>>(out);
}